// round 8
// baseline (speedup 1.0000x reference)
#include <cuda_runtime.h>
#include <math.h>

#define BQ   4096
#define NEX  16384
#define DIN  1024
#define DF   256
#define NLAB 28
#define DC   64
#define SPLITS 8
#define KEYS_PER (NEX/SPLITS)   // 2048

// Scratch (device globals: allocation-free rule)
__device__ float g_Q[(size_t)BQ*DF];     // l2-normalized projected queries
__device__ float g_K[(size_t)NEX*DF];    // l2-normalized projected exemplars
__device__ float g_V[(size_t)NEX*DC];    // exemplar class reps
__device__ float g_num[(size_t)BQ*DC];   // echo numerator
__device__ float g_den[BQ];              // sum |s^3|

// ---------------------------------------------------------------------------
__global__ void zero_kernel(float* out0){
    int i = blockIdx.x*blockDim.x + threadIdx.x;
    int st = gridDim.x*blockDim.x;
    for (int j=i; j<BQ*DC; j+=st) g_num[j] = 0.f;
    for (int j=i; j<BQ;    j+=st) g_den[j] = 0.f;
    if (blockIdx.x==0 && threadIdx.x==0) out0[0] = 0.f;
}

// ---------------------------------------------------------------------------
// C[m][n] = sum_k A[m][k]*B[n][k]   (NT GEMM, both K-major)
// 64x64 tile, BK=16, 16x16 threads, 4x4 fragments
__global__ __launch_bounds__(256) void gemm_nt64(
    const float* __restrict__ A, const float* __restrict__ Bm,
    float* __restrict__ C, int M, int N, int K)
{
    __shared__ float As[16][64];
    __shared__ float Bs[16][64];
    const int tx = threadIdx.x, ty = threadIdx.y;
    const int tid = ty*16 + tx;
    const int m0 = blockIdx.x*64, n0 = blockIdx.y*64;
    const int lrow = tid >> 2;          // 0..63
    const int lk4  = (tid & 3) << 2;    // 0,4,8,12
    const float* Ap = A  + (size_t)(m0+lrow)*K + lk4;
    const float* Bp = Bm + (size_t)(n0+lrow)*K + lk4;
    float acc[4][4] = {};
    for (int kc = 0; kc < K; kc += 16){
        float4 av = *(const float4*)(Ap + kc);
        float4 bv = *(const float4*)(Bp + kc);
        As[lk4+0][lrow]=av.x; As[lk4+1][lrow]=av.y; As[lk4+2][lrow]=av.z; As[lk4+3][lrow]=av.w;
        Bs[lk4+0][lrow]=bv.x; Bs[lk4+1][lrow]=bv.y; Bs[lk4+2][lrow]=bv.z; Bs[lk4+3][lrow]=bv.w;
        __syncthreads();
        #pragma unroll
        for (int k = 0; k < 16; k++){
            float4 aq = *(const float4*)&As[k][ty<<2];
            float4 bq = *(const float4*)&Bs[k][tx<<2];
            float am[4] = {aq.x, aq.y, aq.z, aq.w};
            float bn[4] = {bq.x, bq.y, bq.z, bq.w};
            #pragma unroll
            for (int i = 0; i < 4; i++)
                #pragma unroll
                for (int j = 0; j < 4; j++)
                    acc[i][j] += am[i]*bn[j];
        }
        __syncthreads();
    }
    #pragma unroll
    for (int i = 0; i < 4; i++){
        float4 v = {acc[i][0], acc[i][1], acc[i][2], acc[i][3]};
        *(float4*)(C + (size_t)(m0 + ty*4 + i)*N + n0 + tx*4) = v;
    }
}

// ---------------------------------------------------------------------------
// In-place L2 row normalize, width DF=256, 64 threads/row
__global__ void l2norm_kernel(float* __restrict__ X){
    __shared__ float ws[2];
    const int r = blockIdx.x, t = threadIdx.x;
    float4* row = (float4*)(X + (size_t)r*DF);
    float4 v = row[t];
    float ss = v.x*v.x + v.y*v.y + v.z*v.z + v.w*v.w;
    #pragma unroll
    for (int o = 16; o > 0; o >>= 1) ss += __shfl_down_sync(0xffffffffu, ss, o);
    if ((t & 31) == 0) ws[t>>5] = ss;
    __syncthreads();
    float inv = 1.f / fmaxf(sqrtf(ws[0] + ws[1]), 1e-12f);
    v.x *= inv; v.y *= inv; v.z *= inv; v.w *= inv;
    row[t] = v;
}

// ---------------------------------------------------------------------------
// g_V[r] = l1norm(ex_classes[r]) @ class_reps   (one block per row, 64 thr)
__global__ void exrep_kernel(const float* __restrict__ exc,
                             const float* __restrict__ creps){
    __shared__ float cs[NLAB*DC];
    __shared__ float rowv[NLAB];
    const int r = blockIdx.x, t = threadIdx.x;
    for (int i = t; i < NLAB*DC; i += 64) cs[i] = creps[i];
    if (t < NLAB) rowv[t] = exc[(size_t)r*NLAB + t];
    __syncthreads();
    float s = 0.f;
    #pragma unroll
    for (int k = 0; k < NLAB; k++) s += fabsf(rowv[k]);
    float inv = 1.f / fmaxf(s, 1e-12f);
    float acc = 0.f;
    #pragma unroll
    for (int k = 0; k < NLAB; k++) acc += rowv[k]*cs[k*DC + t];
    g_V[(size_t)r*DC + t] = acc*inv;
}

// ---------------------------------------------------------------------------
// Fused: S = Qblk @ K^T tile, a = s^3, num += a @ V, den += sum|a|
// grid = (BQ/64, SPLITS), 16x16 threads
__global__ __launch_bounds__(256) void attn_kernel(){
    __shared__ float As[16][64];
    __shared__ float Bs[16][64];
    __shared__ float Ps[64][65];   // padded: conflict-free column reads
    __shared__ float Vs[64][64];
    const int tx = threadIdx.x, ty = threadIdx.y;
    const int tid = ty*16 + tx;
    const int q0 = blockIdx.x*64;
    const int kb = blockIdx.y*KEYS_PER;
    const int lrow = tid >> 2, lk4 = (tid & 3) << 2;
    const float* Qp = g_Q + (size_t)(q0+lrow)*DF + lk4;
    float num[4][4] = {};
    float den[4] = {};
    for (int kt = 0; kt < KEYS_PER; kt += 64){
        const int n0 = kb + kt;
        const float* Kp = g_K + (size_t)(n0+lrow)*DF + lk4;
        float sacc[4][4] = {};
        for (int kc = 0; kc < DF; kc += 16){
            float4 av = *(const float4*)(Qp + kc);
            float4 bv = *(const float4*)(Kp + kc);
            As[lk4+0][lrow]=av.x; As[lk4+1][lrow]=av.y; As[lk4+2][lrow]=av.z; As[lk4+3][lrow]=av.w;
            Bs[lk4+0][lrow]=bv.x; Bs[lk4+1][lrow]=bv.y; Bs[lk4+2][lrow]=bv.z; Bs[lk4+3][lrow]=bv.w;
            __syncthreads();
            #pragma unroll
            for (int k = 0; k < 16; k++){
                float4 aq = *(const float4*)&As[k][ty<<2];
                float4 bq = *(const float4*)&Bs[k][tx<<2];
                float am[4] = {aq.x, aq.y, aq.z, aq.w};
                float bn[4] = {bq.x, bq.y, bq.z, bq.w};
                #pragma unroll
                for (int i = 0; i < 4; i++)
                    #pragma unroll
                    for (int j = 0; j < 4; j++)
                        sacc[i][j] += am[i]*bn[j];
            }
            __syncthreads();
        }
        // load V tile (64 keys x 64 dims)
        {
            const int vc  = (tid & 15) << 2;
            const int vr0 = tid >> 4;
            #pragma unroll
            for (int rr = 0; rr < 4; rr++){
                int vr = vr0 + rr*16;
                *(float4*)&Vs[vr][vc] = *(const float4*)&g_V[(size_t)(n0+vr)*DC + vc];
            }
        }
        // transform: a = s^3  (== sign(s)*|s|^3); store P, accumulate den
        #pragma unroll
        for (int i = 0; i < 4; i++)
            #pragma unroll
            for (int j = 0; j < 4; j++){
                float s = sacc[i][j];
                float a = s*s*s;
                den[i] += fabsf(a);
                Ps[ty*4 + i][tx*4 + j] = a;
            }
        __syncthreads();
        // PV: num[m][d] += P[m][n] * V[n][d]
        #pragma unroll 4
        for (int n = 0; n < 64; n++){
            float4 vv = *(const float4*)&Vs[n][tx<<2];
            float p0 = Ps[ty*4+0][n], p1 = Ps[ty*4+1][n];
            float p2 = Ps[ty*4+2][n], p3 = Ps[ty*4+3][n];
            num[0][0]+=p0*vv.x; num[0][1]+=p0*vv.y; num[0][2]+=p0*vv.z; num[0][3]+=p0*vv.w;
            num[1][0]+=p1*vv.x; num[1][1]+=p1*vv.y; num[1][2]+=p1*vv.z; num[1][3]+=p1*vv.w;
            num[2][0]+=p2*vv.x; num[2][1]+=p2*vv.y; num[2][2]+=p2*vv.z; num[2][3]+=p2*vv.w;
            num[3][0]+=p3*vv.x; num[3][1]+=p3*vv.y; num[3][2]+=p3*vv.z; num[3][3]+=p3*vv.w;
        }
        __syncthreads();
    }
    // den: reduce across tx (16 lanes per half-warp), then 1 atomic
    #pragma unroll
    for (int i = 0; i < 4; i++){
        float d = den[i];
        #pragma unroll
        for (int o = 8; o > 0; o >>= 1) d += __shfl_down_sync(0xffffffffu, d, o, 16);
        if (tx == 0) atomicAdd(&g_den[q0 + ty*4 + i], d);
    }
    // num: each thread owns distinct elements; SPLITS-way contention only
    #pragma unroll
    for (int i = 0; i < 4; i++)
        #pragma unroll
        for (int j = 0; j < 4; j++)
            atomicAdd(&g_num[(size_t)(q0 + ty*4 + i)*DC + tx*4 + j], num[i][j]);
}

// ---------------------------------------------------------------------------
// echo = num/max(den,eps); neg_dists = -||echo - class_reps||; BCE mean
// one block (32 threads) per query row
__global__ void loss_kernel(const float* __restrict__ labels,
                            const float* __restrict__ creps,
                            float* __restrict__ out){
    __shared__ float echo_s[DC];
    const int b = blockIdx.x, t = threadIdx.x;
    float inv = 1.f / fmaxf(g_den[b], 1e-12f);
    echo_s[t]      = g_num[(size_t)b*DC + t]      * inv;
    echo_s[t + 32] = g_num[(size_t)b*DC + t + 32] * inv;
    __syncwarp();
    float le = 0.f;
    if (t < NLAB){
        float ss = 0.f;
        #pragma unroll
        for (int d = 0; d < DC; d++){
            float df = echo_s[d] - creps[t*DC + d];
            ss += df*df;
        }
        float x = -sqrtf(ss);                 // neg dist (<= 0)
        out[1 + (size_t)b*NLAB + t] = x;
        float y = labels[(size_t)b*NLAB + t];
        // BCEWithLogits elem: log1p(exp(x)) - y*x   (valid for x<=0)
        le = log1pf(expf(x)) - y*x;
    }
    #pragma unroll
    for (int o = 16; o > 0; o >>= 1) le += __shfl_down_sync(0xffffffffu, le, o);
    if (t == 0) atomicAdd(out, le * (1.f/((float)BQ*(float)NLAB)));
}

// ---------------------------------------------------------------------------
extern "C" void kernel_launch(void* const* d_in, const int* in_sizes, int n_in,
                              void* d_out, int out_size){
    const float* features    = (const float*)d_in[0];
    const float* labels      = (const float*)d_in[1];
    const float* ex_features = (const float*)d_in[2];
    const float* ex_classes  = (const float*)d_in[3];
    const float* g_w         = (const float*)d_in[4];
    const float* class_reps  = (const float*)d_in[5];
    float* out = (float*)d_out;

    float *pQ, *pK;
    cudaGetSymbolAddress((void**)&pQ, g_Q);
    cudaGetSymbolAddress((void**)&pK, g_K);

    zero_kernel<<<1024, 256>>>(out);

    dim3 blk(16, 16);
    gemm_nt64<<<dim3(BQ/64,  DF/64), blk>>>(features,    g_w, pQ, BQ,  DF, DIN);
    gemm_nt64<<<dim3(NEX/64, DF/64), blk>>>(ex_features, g_w, pK, NEX, DF, DIN);
    l2norm_kernel<<<BQ,  64>>>(pQ);
    l2norm_kernel<<<NEX, 64>>>(pK);
    exrep_kernel<<<NEX, 64>>>(ex_classes, class_reps);
    attn_kernel<<<dim3(BQ/64, SPLITS), blk>>>();
    loss_kernel<<<BQ, 32>>>(labels, class_reps, out);
}

// round 10
// speedup vs baseline: 3.7995x; 3.7995x over previous
#include <cuda_runtime.h>
#include <math.h>
#include <stdint.h>

#define BQ   4096
#define NEX  16384
#define DIN  1024
#define DF   256
#define NLAB 28
#define DC   64
#define PV_SPLITS 8
#define KSPLIT (NEX/PV_SPLITS)   // 2048

// ---------------- scratch (device globals: allocation-free rule) ----------
__device__ float g_Q[(size_t)BQ*DF];            // l2-normed projected queries (tf32 bits)
__device__ float g_K[(size_t)NEX*DF];           // l2-normed projected exemplars (tf32 bits)
__device__ float g_A[(size_t)BQ*NEX];           // a = s^3 (tf32 bits)
__device__ float g_Vt[(size_t)DC*NEX];          // V transposed (tf32 bits)
__device__ float g_num8[(size_t)PV_SPLITS*BQ*DC];
__device__ float g_den[BQ];

// ---------------- helpers ---------------------------------------------------
__device__ __forceinline__ float cvt_tf32(float x){
    uint32_t u;
    asm("cvt.rna.tf32.f32 %0, %1;" : "=r"(u) : "f"(x));
    return __uint_as_float(u);
}
__device__ __forceinline__ void mma_tf32(float c[4], const uint32_t a[4], const uint32_t b[2]){
    asm volatile(
        "mma.sync.aligned.m16n8k8.row.col.f32.tf32.tf32.f32 "
        "{%0,%1,%2,%3}, {%4,%5,%6,%7}, {%8,%9}, {%0,%1,%2,%3};\n"
        : "+f"(c[0]), "+f"(c[1]), "+f"(c[2]), "+f"(c[3])
        : "r"(a[0]), "r"(a[1]), "r"(a[2]), "r"(a[3]), "r"(b[0]), "r"(b[1]));
}
__device__ __forceinline__ uint32_t fbits(float f){ return __float_as_uint(f); }

// SMEM geometry: padded stride 36 floats (144B, 16B-aligned, conflict-free frags)
#define SPAD 36
#define AS_BUF (128*SPAD)     // floats per A buffer

// ---------------------------------------------------------------------------
// Generic double-buffered tf32 GEMM mainloop.
// C[m][n] = sum_k A[m][k]*B[n][k]  (NT; both row-major, K contiguous)
// BM=128, BN = NWF*32 (NWF=4 -> 128, NWF=2 -> 64), BK=32, 256 threads,
// warps 2(M) x 4(N), warp tile 64 x (NWF*8).
// Ag/Bg pre-offset to (m0, k0)/(n0, k0). NK = K/32 iterations.
template<int NWF, bool CVT>
__device__ __forceinline__ void gemm_main(const float* __restrict__ Ag,
                                          const float* __restrict__ Bg,
                                          int lda, int ldb, int NK,
                                          float* sm, float acc[4][NWF][4])
{
    const int tid = threadIdx.x, lid = tid & 31, wid = tid >> 5;
    const int wm = wid & 1, wn = wid >> 1;
    const int g = lid >> 2, tig = lid & 3;
    constexpr int BROWS = NWF * 32;          // B tile rows (128 or 64)
    float* As = sm;
    float* Bs = sm + 2*AS_BUF;
    const int r0 = tid >> 3;                  // 0..31
    const int j  = tid & 7;                   // float4 slot in 32-float row

    float4 areg[4], breg[NWF];

    auto LDG = [&](int kc){
        const float* ap = Ag + (size_t)r0*lda + kc*32 + j*4;
        #pragma unroll
        for (int i = 0; i < 4; i++) areg[i] = *(const float4*)(ap + (size_t)(i*32)*lda);
        const float* bp = Bg + (size_t)r0*ldb + kc*32 + j*4;
        #pragma unroll
        for (int i = 0; i < NWF; i++) breg[i] = *(const float4*)(bp + (size_t)(i*32)*ldb);
    };
    auto STS = [&](int buf){
        #pragma unroll
        for (int i = 0; i < 4; i++){
            float4 v = areg[i];
            if (CVT){ v.x=cvt_tf32(v.x); v.y=cvt_tf32(v.y); v.z=cvt_tf32(v.z); v.w=cvt_tf32(v.w); }
            *(float4*)(As + buf*AS_BUF + (r0 + i*32)*SPAD + j*4) = v;
        }
        #pragma unroll
        for (int i = 0; i < NWF; i++){
            float4 v = breg[i];
            if (CVT){ v.x=cvt_tf32(v.x); v.y=cvt_tf32(v.y); v.z=cvt_tf32(v.z); v.w=cvt_tf32(v.w); }
            *(float4*)(Bs + buf*(BROWS*SPAD) + (r0 + i*32)*SPAD + j*4) = v;
        }
    };

    LDG(0); STS(0);
    __syncthreads();

    for (int kc = 0; kc < NK; kc++){
        const int buf = kc & 1;
        if (kc + 1 < NK) LDG(kc + 1);
        const float* Ab = As + buf*AS_BUF;
        const float* Bb = Bs + buf*(BROWS*SPAD);
        #pragma unroll
        for (int ks = 0; ks < 4; ks++){
            uint32_t af[4][4];
            #pragma unroll
            for (int mf = 0; mf < 4; mf++){
                const int row = wm*64 + mf*16 + g;
                const int col = ks*8 + tig;
                af[mf][0] = fbits(Ab[row*SPAD + col]);
                af[mf][1] = fbits(Ab[(row+8)*SPAD + col]);
                af[mf][2] = fbits(Ab[row*SPAD + col + 4]);
                af[mf][3] = fbits(Ab[(row+8)*SPAD + col + 4]);
            }
            uint32_t bf[NWF][2];
            #pragma unroll
            for (int nf = 0; nf < NWF; nf++){
                const int n = wn*(NWF*8) + nf*8 + g;
                bf[nf][0] = fbits(Bb[n*SPAD + ks*8 + tig]);
                bf[nf][1] = fbits(Bb[n*SPAD + ks*8 + tig + 4]);
            }
            #pragma unroll
            for (int mf = 0; mf < 4; mf++)
                #pragma unroll
                for (int nf = 0; nf < NWF; nf++)
                    mma_tf32(acc[mf][nf], af[mf], bf[nf]);
        }
        if (kc + 1 < NK){
            __syncthreads();
            STS((kc + 1) & 1);
            __syncthreads();
        }
    }
}

// ---------------------------------------------------------------------------
__global__ void zero_kernel(float* out0){
    int i = blockIdx.x*blockDim.x + threadIdx.x;
    if (i < BQ) g_den[i] = 0.f;
    if (i == 0) out0[0] = 0.f;
}

// ---------------------------------------------------------------------------
// projection: C = A @ W^T (fp32 out; normalize+tf32-round done by l2norm)
__global__ __launch_bounds__(256, 1) void proj_kernel(const float* __restrict__ A,
                                                      const float* __restrict__ W,
                                                      float* __restrict__ C){
    extern __shared__ float sm[];
    const int m0 = blockIdx.x * 128, n0 = blockIdx.y * 128;
    float acc[4][4][4] = {};
    gemm_main<4, true>(A + (size_t)m0*DIN, W + (size_t)n0*DIN, DIN, DIN, DIN/32, sm, acc);

    const int lid = threadIdx.x & 31, wid = threadIdx.x >> 5;
    const int wm = wid & 1, wn = wid >> 1;
    const int g = lid >> 2, tig = lid & 3;
    #pragma unroll
    for (int mf = 0; mf < 4; mf++){
        const int rlo = m0 + wm*64 + mf*16 + g;
        #pragma unroll
        for (int nf = 0; nf < 4; nf++){
            const int cb = n0 + wn*32 + nf*8 + tig*2;
            *(float2*)(C + (size_t)rlo*DF + cb)     = make_float2(acc[mf][nf][0], acc[mf][nf][1]);
            *(float2*)(C + (size_t)(rlo+8)*DF + cb) = make_float2(acc[mf][nf][2], acc[mf][nf][3]);
        }
    }
}

// ---------------------------------------------------------------------------
// In-place L2 row normalize + tf32 round, width DF=256, 64 threads/row
__global__ void l2norm_kernel(float* __restrict__ X){
    __shared__ float ws[2];
    const int r = blockIdx.x, t = threadIdx.x;
    float4* row = (float4*)(X + (size_t)r*DF);
    float4 v = row[t];
    float ss = v.x*v.x + v.y*v.y + v.z*v.z + v.w*v.w;
    #pragma unroll
    for (int o = 16; o > 0; o >>= 1) ss += __shfl_down_sync(0xffffffffu, ss, o);
    if ((t & 31) == 0) ws[t>>5] = ss;
    __syncthreads();
    float inv = 1.f / fmaxf(sqrtf(ws[0] + ws[1]), 1e-12f);
    v.x = cvt_tf32(v.x*inv); v.y = cvt_tf32(v.y*inv);
    v.z = cvt_tf32(v.z*inv); v.w = cvt_tf32(v.w*inv);
    row[t] = v;
}

// ---------------------------------------------------------------------------
// g_Vt[d][r] = (l1norm(ex_classes[r]) @ class_reps)[d], tf32-rounded
__global__ void exrep_kernel(const float* __restrict__ exc,
                             const float* __restrict__ creps){
    __shared__ float cs[NLAB*DC];
    __shared__ float rowv[NLAB];
    const int r = blockIdx.x, t = threadIdx.x;
    for (int i = t; i < NLAB*DC; i += 64) cs[i] = creps[i];
    if (t < NLAB) rowv[t] = exc[(size_t)r*NLAB + t];
    __syncthreads();
    float s = 0.f;
    #pragma unroll
    for (int k = 0; k < NLAB; k++) s += fabsf(rowv[k]);
    float inv = 1.f / fmaxf(s, 1e-12f);
    float acc = 0.f;
    #pragma unroll
    for (int k = 0; k < NLAB; k++) acc += rowv[k]*cs[k*DC + t];
    g_Vt[(size_t)t*NEX + r] = cvt_tf32(acc*inv);
}

// ---------------------------------------------------------------------------
// S GEMM: s = Q tile . K tile^T ; a = s^3 -> g_A (tf32) ; g_den += sum|a|
__global__ __launch_bounds__(256, 1) void sgemm_kernel(){
    extern __shared__ float sm[];
    const int m0 = blockIdx.x * 128, n0 = blockIdx.y * 128;
    float acc[4][4][4] = {};
    gemm_main<4, false>(g_Q + (size_t)m0*DF, g_K + (size_t)n0*DF, DF, DF, DF/32, sm, acc);

    const int tid = threadIdx.x, lid = tid & 31, wid = tid >> 5;
    const int wm = wid & 1, wn = wid >> 1;
    const int g = lid >> 2, tig = lid & 3;

    float* sden = sm;                // smem free after mainloop
    __syncthreads();
    if (tid < 128) sden[tid] = 0.f;
    __syncthreads();

    #pragma unroll
    for (int mf = 0; mf < 4; mf++){
        const int rlo = m0 + wm*64 + mf*16 + g;
        float d0 = 0.f, d1 = 0.f;
        #pragma unroll
        for (int nf = 0; nf < 4; nf++){
            const int cb = n0 + wn*32 + nf*8 + tig*2;
            float s0 = acc[mf][nf][0], s1 = acc[mf][nf][1];
            float s2 = acc[mf][nf][2], s3 = acc[mf][nf][3];
            float a0 = s0*s0*s0, a1 = s1*s1*s1, a2 = s2*s2*s2, a3 = s3*s3*s3;
            d0 += fabsf(a0) + fabsf(a1);
            d1 += fabsf(a2) + fabsf(a3);
            *(float2*)(g_A + (size_t)rlo*NEX + cb)     = make_float2(cvt_tf32(a0), cvt_tf32(a1));
            *(float2*)(g_A + (size_t)(rlo+8)*NEX + cb) = make_float2(cvt_tf32(a2), cvt_tf32(a3));
        }
        d0 += __shfl_xor_sync(0xffffffffu, d0, 1);
        d0 += __shfl_xor_sync(0xffffffffu, d0, 2);
        d1 += __shfl_xor_sync(0xffffffffu, d1, 1);
        d1 += __shfl_xor_sync(0xffffffffu, d1, 2);
        if (tig == 0){
            atomicAdd(&sden[wm*64 + mf*16 + g], d0);
            atomicAdd(&sden[wm*64 + mf*16 + g + 8], d1);
        }
    }
    __syncthreads();
    if (tid < 128) atomicAdd(&g_den[m0 + tid], sden[tid]);
}

// ---------------------------------------------------------------------------
// PV GEMM: num8[split][m][d] = sum_{k in split} a[m][k] * Vt[d][k]
__global__ __launch_bounds__(256, 1) void pv_kernel(){
    extern __shared__ float sm[];
    const int m0 = blockIdx.x * 128;
    const int split = blockIdx.y;
    const int k0 = split * KSPLIT;
    float acc[4][2][4] = {};
    gemm_main<2, false>(g_A + (size_t)m0*NEX + k0, g_Vt + k0, NEX, NEX, KSPLIT/32, sm, acc);

    const int lid = threadIdx.x & 31, wid = threadIdx.x >> 5;
    const int wm = wid & 1, wn = wid >> 1;
    const int g = lid >> 2, tig = lid & 3;
    float* outb = g_num8 + (size_t)split*BQ*DC;
    #pragma unroll
    for (int mf = 0; mf < 4; mf++){
        const int rlo = m0 + wm*64 + mf*16 + g;
        #pragma unroll
        for (int nf = 0; nf < 2; nf++){
            const int cb = wn*16 + nf*8 + tig*2;
            *(float2*)(outb + (size_t)rlo*DC + cb)     = make_float2(acc[mf][nf][0], acc[mf][nf][1]);
            *(float2*)(outb + (size_t)(rlo+8)*DC + cb) = make_float2(acc[mf][nf][2], acc[mf][nf][3]);
        }
    }
}

// ---------------------------------------------------------------------------
// echo = (sum_splits num8)/max(den,eps); neg_dists = -||echo - class_reps||; BCE mean
__global__ void loss_kernel(const float* __restrict__ labels,
                            const float* __restrict__ creps,
                            float* __restrict__ out){
    __shared__ float echo_s[DC];
    const int b = blockIdx.x, t = threadIdx.x;
    float inv = 1.f / fmaxf(g_den[b], 1e-12f);
    float n0 = 0.f, n1 = 0.f;
    #pragma unroll
    for (int s = 0; s < PV_SPLITS; s++){
        const float* p = g_num8 + ((size_t)s*BQ + b)*DC;
        n0 += p[t];
        n1 += p[t + 32];
    }
    echo_s[t]      = n0 * inv;
    echo_s[t + 32] = n1 * inv;
    __syncwarp();
    float le = 0.f;
    if (t < NLAB){
        float ss = 0.f;
        #pragma unroll
        for (int d = 0; d < DC; d++){
            float df = echo_s[d] - creps[t*DC + d];
            ss += df*df;
        }
        float x = -sqrtf(ss);
        out[1 + (size_t)b*NLAB + t] = x;
        float y = labels[(size_t)b*NLAB + t];
        le = log1pf(expf(x)) - y*x;
    }
    #pragma unroll
    for (int o = 16; o > 0; o >>= 1) le += __shfl_down_sync(0xffffffffu, le, o);
    if (t == 0) atomicAdd(out, le * (1.f/((float)BQ*(float)NLAB)));
}

// ---------------------------------------------------------------------------
#define SMEM_G128 ((2*AS_BUF + 2*128*SPAD)*4)          // 73728 B
#define SMEM_SG   (SMEM_G128 + 512)                    // + sden
#define SMEM_PV   ((2*AS_BUF + 2*64*SPAD)*4)           // 55296 B

extern "C" void kernel_launch(void* const* d_in, const int* in_sizes, int n_in,
                              void* d_out, int out_size){
    const float* features    = (const float*)d_in[0];
    const float* labels      = (const float*)d_in[1];
    const float* ex_features = (const float*)d_in[2];
    const float* ex_classes  = (const float*)d_in[3];
    const float* g_w         = (const float*)d_in[4];
    const float* class_reps  = (const float*)d_in[5];
    float* out = (float*)d_out;

    float *pQ, *pK;
    cudaGetSymbolAddress((void**)&pQ, g_Q);
    cudaGetSymbolAddress((void**)&pK, g_K);

    static int attr_done = 0;
    if (!attr_done){
        cudaFuncSetAttribute(proj_kernel,  cudaFuncAttributeMaxDynamicSharedMemorySize, SMEM_G128);
        cudaFuncSetAttribute(sgemm_kernel, cudaFuncAttributeMaxDynamicSharedMemorySize, SMEM_SG);
        cudaFuncSetAttribute(pv_kernel,    cudaFuncAttributeMaxDynamicSharedMemorySize, SMEM_PV);
        attr_done = 1;
    }

    zero_kernel<<<(BQ + 255)/256, 256>>>(out);

    proj_kernel<<<dim3(BQ/128,  2), 256, SMEM_G128>>>(features,    g_w, pQ);
    proj_kernel<<<dim3(NEX/128, 2), 256, SMEM_G128>>>(ex_features, g_w, pK);
    l2norm_kernel<<<BQ,  64>>>(pQ);
    l2norm_kernel<<<NEX, 64>>>(pK);
    exrep_kernel<<<NEX, 64>>>(ex_classes, class_reps);
    sgemm_kernel<<<dim3(BQ/128, NEX/128), 256, SMEM_SG>>>();
    pv_kernel<<<dim3(BQ/128, PV_SPLITS), 256, SMEM_PV>>>();
    loss_kernel<<<BQ, 32>>>(labels, class_reps, out);
}

// round 11
// speedup vs baseline: 5.2053x; 1.3700x over previous
#include <cuda_runtime.h>
#include <cuda_bf16.h>
#include <math.h>
#include <stdint.h>

#define BQ   4096
#define NEX  16384
#define DIN  1024
#define DF   256
#define NLAB 28
#define DC   64
#define PV_SPLITS 8
#define KSPLIT (NEX/PV_SPLITS)   // 2048

// ---------------- scratch (device globals: allocation-free rule) ----------
__device__ float          g_F[(size_t)NEX*DF];        // proj output (fp32, pre-norm)
__device__ __nv_bfloat16  g_Qh[(size_t)BQ*DF];        // l2-normed queries (bf16)
__device__ __nv_bfloat16  g_Kh[(size_t)NEX*DF];       // l2-normed exemplars (bf16)
__device__ __nv_bfloat16  g_A[(size_t)BQ*NEX];        // a = s^3 (bf16)
__device__ __nv_bfloat16  g_Vt[(size_t)DC*NEX];       // V transposed (bf16)
__device__ float          g_num8[(size_t)PV_SPLITS*BQ*DC];
__device__ float          g_den[BQ];

// ---------------- helpers ---------------------------------------------------
__device__ __forceinline__ void mma_bf16(float c[4], const uint32_t a[4], const uint32_t b[2]){
    asm volatile(
        "mma.sync.aligned.m16n8k16.row.col.f32.bf16.bf16.f32 "
        "{%0,%1,%2,%3}, {%4,%5,%6,%7}, {%8,%9}, {%0,%1,%2,%3};\n"
        : "+f"(c[0]), "+f"(c[1]), "+f"(c[2]), "+f"(c[3])
        : "r"(a[0]), "r"(a[1]), "r"(a[2]), "r"(a[3]), "r"(b[0]), "r"(b[1]));
}
__device__ __forceinline__ uint32_t ldsm_u32(const __nv_bfloat16* p){
    return *(const uint32_t*)p;
}
__device__ __forceinline__ uint32_t pack_bf16(float x, float y){
    __nv_bfloat162 h = __floats2bfloat162_rn(x, y);
    return *(uint32_t*)&h;
}

// SMEM row stride: 40 bf16 (80B). Fragment LDS conflict-free (20g mod 32 spread).
#define SSTR 40
#define ABUF (128*SSTR)

// ---------------------------------------------------------------------------
// Double-buffered bf16 GEMM mainloop. C[m][n] = sum_k A[m][k]*B[n][k] (NT).
// BM=128, BN=NWF*32, BK=32, 256 threads, warps 2(M)x4(N), warp tile 64x(NWF*8).
// SRCF32: global source is fp32 (converted to bf16 in STS); else bf16 source.
// lda/ldb in elements of the source type. NK = K/32.
template<int NWF, bool SRCF32>
__device__ __forceinline__ void gemm_bf16_main(const void* __restrict__ Agv,
                                               const void* __restrict__ Bgv,
                                               int lda, int ldb, int NK,
                                               __nv_bfloat16* As, __nv_bfloat16* Bs,
                                               float acc[4][NWF][4])
{
    const int tid = threadIdx.x, lid = tid & 31, wid = tid >> 5;
    const int wm = wid & 1, wn = wid >> 1;
    const int g = lid >> 2, tig = lid & 3;
    constexpr int BROWS = NWF * 32;
    constexpr int BBUF = BROWS * SSTR;

    float4 af[4], bf4[NWF];                 // SRCF32 staging
    uint4  ah[2], bh[(NWF + 1) / 2];        // bf16-src staging

    auto LDG = [&](int kc){
        if (SRCF32){
            const float* Ag = (const float*)Agv;
            const float* Bg = (const float*)Bgv;
            const int r0 = tid >> 3, j = tid & 7;
            #pragma unroll
            for (int i = 0; i < 4; i++)
                af[i] = *(const float4*)(Ag + (size_t)(r0 + i*32)*lda + kc*32 + j*4);
            #pragma unroll
            for (int i = 0; i < NWF; i++)
                bf4[i] = *(const float4*)(Bg + (size_t)(r0 + i*32)*ldb + kc*32 + j*4);
        } else {
            const __nv_bfloat16* Ag = (const __nv_bfloat16*)Agv;
            const __nv_bfloat16* Bg = (const __nv_bfloat16*)Bgv;
            const int r = tid >> 2, q = tid & 3;
            #pragma unroll
            for (int i = 0; i < 2; i++)
                ah[i] = *(const uint4*)(Ag + (size_t)(r + i*64)*lda + kc*32 + q*8);
            #pragma unroll
            for (int i = 0; i < NWF/2; i++)
                bh[i] = *(const uint4*)(Bg + (size_t)(r + i*64)*ldb + kc*32 + q*8);
        }
    };
    auto STS = [&](int buf){
        if (SRCF32){
            const int r0 = tid >> 3, j = tid & 7;
            #pragma unroll
            for (int i = 0; i < 4; i++){
                uint2 v = { pack_bf16(af[i].x, af[i].y), pack_bf16(af[i].z, af[i].w) };
                *(uint2*)(As + buf*ABUF + (r0 + i*32)*SSTR + j*4) = v;
            }
            #pragma unroll
            for (int i = 0; i < NWF; i++){
                uint2 v = { pack_bf16(bf4[i].x, bf4[i].y), pack_bf16(bf4[i].z, bf4[i].w) };
                *(uint2*)(Bs + buf*BBUF + (r0 + i*32)*SSTR + j*4) = v;
            }
        } else {
            const int r = tid >> 2, q = tid & 3;
            #pragma unroll
            for (int i = 0; i < 2; i++)
                *(uint4*)(As + buf*ABUF + (r + i*64)*SSTR + q*8) = ah[i];
            #pragma unroll
            for (int i = 0; i < NWF/2; i++)
                *(uint4*)(Bs + buf*BBUF + (r + i*64)*SSTR + q*8) = bh[i];
        }
    };

    LDG(0); STS(0);
    __syncthreads();

    for (int kc = 0; kc < NK; kc++){
        const int buf = kc & 1;
        if (kc + 1 < NK) LDG(kc + 1);
        const __nv_bfloat16* Ab = As + buf*ABUF;
        const __nv_bfloat16* Bb = Bs + buf*BBUF;
        #pragma unroll
        for (int ks = 0; ks < 2; ks++){
            uint32_t afr[4][4];
            #pragma unroll
            for (int mf = 0; mf < 4; mf++){
                const int row = wm*64 + mf*16 + g;
                const int col = ks*16 + 2*tig;
                afr[mf][0] = ldsm_u32(Ab + row*SSTR + col);
                afr[mf][1] = ldsm_u32(Ab + (row+8)*SSTR + col);
                afr[mf][2] = ldsm_u32(Ab + row*SSTR + col + 8);
                afr[mf][3] = ldsm_u32(Ab + (row+8)*SSTR + col + 8);
            }
            uint32_t bfr[NWF][2];
            #pragma unroll
            for (int nf = 0; nf < NWF; nf++){
                const int n = wn*(NWF*8) + nf*8 + g;
                bfr[nf][0] = ldsm_u32(Bb + n*SSTR + ks*16 + 2*tig);
                bfr[nf][1] = ldsm_u32(Bb + n*SSTR + ks*16 + 2*tig + 8);
            }
            #pragma unroll
            for (int mf = 0; mf < 4; mf++)
                #pragma unroll
                for (int nf = 0; nf < NWF; nf++)
                    mma_bf16(acc[mf][nf], afr[mf], bfr[nf]);
        }
        if (kc + 1 < NK){
            __syncthreads();
            STS((kc + 1) & 1);
            __syncthreads();
        }
    }
}

// ---------------------------------------------------------------------------
__global__ void zero_kernel(float* out0){
    int i = blockIdx.x*blockDim.x + threadIdx.x;
    if (i < BQ) g_den[i] = 0.f;
    if (i == 0) out0[0] = 0.f;
}

// ---------------------------------------------------------------------------
// projection: g_F = A @ W^T (fp32 accum out; bf16 compute)
__global__ __launch_bounds__(256) void proj_kernel(const float* __restrict__ A,
                                                   const float* __restrict__ W){
    __shared__ __nv_bfloat16 As[2*ABUF];
    __shared__ __nv_bfloat16 Bs[2*128*SSTR];
    const int m0 = blockIdx.x * 128, n0 = blockIdx.y * 128;
    float acc[4][4][4] = {};
    gemm_bf16_main<4, true>(A + (size_t)m0*DIN, W + (size_t)n0*DIN, DIN, DIN, DIN/32, As, Bs, acc);

    const int lid = threadIdx.x & 31, wid = threadIdx.x >> 5;
    const int wm = wid & 1, wn = wid >> 1;
    const int g = lid >> 2, tig = lid & 3;
    #pragma unroll
    for (int mf = 0; mf < 4; mf++){
        const int rlo = m0 + wm*64 + mf*16 + g;
        #pragma unroll
        for (int nf = 0; nf < 4; nf++){
            const int cb = n0 + wn*32 + nf*8 + tig*2;
            *(float2*)(g_F + (size_t)rlo*DF + cb)     = make_float2(acc[mf][nf][0], acc[mf][nf][1]);
            *(float2*)(g_F + (size_t)(rlo+8)*DF + cb) = make_float2(acc[mf][nf][2], acc[mf][nf][3]);
        }
    }
}

// ---------------------------------------------------------------------------
// L2 row normalize fp32 -> bf16, width DF=256, 64 threads/row
__global__ void l2norm_kernel(__nv_bfloat16* __restrict__ outp){
    __shared__ float ws[2];
    const int r = blockIdx.x, t = threadIdx.x;
    float4 v = *(const float4*)(g_F + (size_t)r*DF + t*4);
    float ss = v.x*v.x + v.y*v.y + v.z*v.z + v.w*v.w;
    #pragma unroll
    for (int o = 16; o > 0; o >>= 1) ss += __shfl_down_sync(0xffffffffu, ss, o);
    if ((t & 31) == 0) ws[t>>5] = ss;
    __syncthreads();
    float inv = 1.f / fmaxf(sqrtf(ws[0] + ws[1]), 1e-12f);
    uint2 o = { pack_bf16(v.x*inv, v.y*inv), pack_bf16(v.z*inv, v.w*inv) };
    *(uint2*)(outp + (size_t)r*DF + t*4) = o;
}

// ---------------------------------------------------------------------------
// g_Vt[d][r] = (l1norm(ex_classes[r]) @ class_reps)[d], bf16
__global__ void exrep_kernel(const float* __restrict__ exc,
                             const float* __restrict__ creps){
    __shared__ float cs[NLAB*DC];
    __shared__ float rowv[NLAB];
    const int r = blockIdx.x, t = threadIdx.x;
    for (int i = t; i < NLAB*DC; i += 64) cs[i] = creps[i];
    if (t < NLAB) rowv[t] = exc[(size_t)r*NLAB + t];
    __syncthreads();
    float s = 0.f;
    #pragma unroll
    for (int k = 0; k < NLAB; k++) s += fabsf(rowv[k]);
    float inv = 1.f / fmaxf(s, 1e-12f);
    float acc = 0.f;
    #pragma unroll
    for (int k = 0; k < NLAB; k++) acc += rowv[k]*cs[k*DC + t];
    g_Vt[(size_t)t*NEX + r] = __float2bfloat16_rn(acc*inv);
}

// ---------------------------------------------------------------------------
// S GEMM: s = Q tile . K tile^T ; a = s^3 -> g_A (bf16) ; g_den += sum|a|
__global__ __launch_bounds__(256) void sgemm_kernel(){
    __shared__ __nv_bfloat16 As[2*ABUF];
    __shared__ __nv_bfloat16 Bs[2*128*SSTR];
    const int m0 = blockIdx.x * 128, n0 = blockIdx.y * 128;
    float acc[4][4][4] = {};
    gemm_bf16_main<4, false>(g_Qh + (size_t)m0*DF, g_Kh + (size_t)n0*DF, DF, DF, DF/32, As, Bs, acc);

    const int tid = threadIdx.x, lid = tid & 31, wid = tid >> 5;
    const int wm = wid & 1, wn = wid >> 1;
    const int g = lid >> 2, tig = lid & 3;

    float* sden = (float*)As;          // smem free after mainloop
    __syncthreads();
    if (tid < 128) sden[tid] = 0.f;
    __syncthreads();

    #pragma unroll
    for (int mf = 0; mf < 4; mf++){
        const int rlo = m0 + wm*64 + mf*16 + g;
        float d0 = 0.f, d1 = 0.f;
        #pragma unroll
        for (int nf = 0; nf < 4; nf++){
            const int cb = n0 + wn*32 + nf*8 + tig*2;
            float s0 = acc[mf][nf][0], s1 = acc[mf][nf][1];
            float s2 = acc[mf][nf][2], s3 = acc[mf][nf][3];
            float a0 = s0*s0*s0, a1 = s1*s1*s1, a2 = s2*s2*s2, a3 = s3*s3*s3;
            d0 += fabsf(a0) + fabsf(a1);
            d1 += fabsf(a2) + fabsf(a3);
            *(uint32_t*)(g_A + (size_t)rlo*NEX + cb)     = pack_bf16(a0, a1);
            *(uint32_t*)(g_A + (size_t)(rlo+8)*NEX + cb) = pack_bf16(a2, a3);
        }
        d0 += __shfl_xor_sync(0xffffffffu, d0, 1);
        d0 += __shfl_xor_sync(0xffffffffu, d0, 2);
        d1 += __shfl_xor_sync(0xffffffffu, d1, 1);
        d1 += __shfl_xor_sync(0xffffffffu, d1, 2);
        if (tig == 0){
            atomicAdd(&sden[wm*64 + mf*16 + g], d0);
            atomicAdd(&sden[wm*64 + mf*16 + g + 8], d1);
        }
    }
    __syncthreads();
    if (tid < 128) atomicAdd(&g_den[m0 + tid], sden[tid]);
}

// ---------------------------------------------------------------------------
// PV GEMM: num8[split][m][d] = sum_{k in split} a[m][k] * Vt[d][k]
__global__ __launch_bounds__(256) void pv_kernel(){
    __shared__ __nv_bfloat16 As[2*ABUF];
    __shared__ __nv_bfloat16 Bs[2*64*SSTR];
    const int m0 = blockIdx.x * 128;
    const int split = blockIdx.y;
    const int k0 = split * KSPLIT;
    float acc[4][2][4] = {};
    gemm_bf16_main<2, false>(g_A + (size_t)m0*NEX + k0, g_Vt + k0, NEX, NEX, KSPLIT/32, As, Bs, acc);

    const int lid = threadIdx.x & 31, wid = threadIdx.x >> 5;
    const int wm = wid & 1, wn = wid >> 1;
    const int g = lid >> 2, tig = lid & 3;
    float* outb = g_num8 + (size_t)split*BQ*DC;
    #pragma unroll
    for (int mf = 0; mf < 4; mf++){
        const int rlo = m0 + wm*64 + mf*16 + g;
        #pragma unroll
        for (int nf = 0; nf < 2; nf++){
            const int cb = wn*16 + nf*8 + tig*2;
            *(float2*)(outb + (size_t)rlo*DC + cb)     = make_float2(acc[mf][nf][0], acc[mf][nf][1]);
            *(float2*)(outb + (size_t)(rlo+8)*DC + cb) = make_float2(acc[mf][nf][2], acc[mf][nf][3]);
        }
    }
}

// ---------------------------------------------------------------------------
// echo = (sum_splits num8)/max(den,eps); neg_dists = -||echo - class_reps||; BCE mean
__global__ void loss_kernel(const float* __restrict__ labels,
                            const float* __restrict__ creps,
                            float* __restrict__ out){
    __shared__ float echo_s[DC];
    const int b = blockIdx.x, t = threadIdx.x;
    float inv = 1.f / fmaxf(g_den[b], 1e-12f);
    float n0 = 0.f, n1 = 0.f;
    #pragma unroll
    for (int s = 0; s < PV_SPLITS; s++){
        const float* p = g_num8 + ((size_t)s*BQ + b)*DC;
        n0 += p[t];
        n1 += p[t + 32];
    }
    echo_s[t]      = n0 * inv;
    echo_s[t + 32] = n1 * inv;
    __syncwarp();
    float le = 0.f;
    if (t < NLAB){
        float ss = 0.f;
        #pragma unroll
        for (int d = 0; d < DC; d++){
            float df = echo_s[d] - creps[t*DC + d];
            ss += df*df;
        }
        float x = -sqrtf(ss);
        out[1 + (size_t)b*NLAB + t] = x;
        float y = labels[(size_t)b*NLAB + t];
        le = log1pf(expf(x)) - y*x;
    }
    #pragma unroll
    for (int o = 16; o > 0; o >>= 1) le += __shfl_down_sync(0xffffffffu, le, o);
    if (t == 0) atomicAdd(out, le * (1.f/((float)BQ*(float)NLAB)));
}

// ---------------------------------------------------------------------------
extern "C" void kernel_launch(void* const* d_in, const int* in_sizes, int n_in,
                              void* d_out, int out_size){
    const float* features    = (const float*)d_in[0];
    const float* labels      = (const float*)d_in[1];
    const float* ex_features = (const float*)d_in[2];
    const float* ex_classes  = (const float*)d_in[3];
    const float* g_w         = (const float*)d_in[4];
    const float* class_reps  = (const float*)d_in[5];
    float* out = (float*)d_out;

    __nv_bfloat16 *pQ, *pK;
    cudaGetSymbolAddress((void**)&pQ, g_Qh);
    cudaGetSymbolAddress((void**)&pK, g_Kh);

    zero_kernel<<<(BQ + 255)/256, 256>>>(out);

    // Q path (g_F is reused, so order matters: proj -> l2norm before next proj)
    proj_kernel<<<dim3(BQ/128, 2), 256>>>(features, g_w);
    l2norm_kernel<<<BQ, 64>>>(pQ);
    // K path
    proj_kernel<<<dim3(NEX/128, 2), 256>>>(ex_features, g_w);
    l2norm_kernel<<<NEX, 64>>>(pK);

    exrep_kernel<<<NEX, 64>>>(ex_classes, class_reps);
    sgemm_kernel<<<dim3(BQ/128, NEX/128), 256>>>();
    pv_kernel<<<dim3(BQ/128, PV_SPLITS), 256>>>();
    loss_kernel<<<BQ, 32>>>(labels, class_reps, out);
}

// round 12
// speedup vs baseline: 6.2667x; 1.2039x over previous
#include <cuda_runtime.h>
#include <cuda_bf16.h>
#include <math.h>
#include <stdint.h>

#define BQ   4096
#define NEX  16384
#define DIN  1024
#define DF   256
#define NLAB 28
#define DC   64
#define PV_SPLITS 8
#define KSPLIT (NEX/PV_SPLITS)   // 2048
#define TILES (KSPLIT/128)       // 16

// ---------------- scratch (device globals: allocation-free rule) ----------
__device__ float          g_F[(size_t)NEX*DF];        // proj output (fp32, pre-norm)
__device__ __nv_bfloat16  g_Qh[(size_t)BQ*DF];        // l2-normed queries (bf16)
__device__ __nv_bfloat16  g_Kh[(size_t)NEX*DF];       // l2-normed exemplars (bf16)
__device__ __nv_bfloat16  g_Vt[(size_t)DC*NEX];       // V transposed (bf16)
__device__ float          g_num8[(size_t)PV_SPLITS*BQ*DC];
__device__ float          g_den[BQ];

// ---------------- helpers ---------------------------------------------------
__device__ __forceinline__ void mma_bf16(float c[4], const uint32_t a[4], const uint32_t b[2]){
    asm volatile(
        "mma.sync.aligned.m16n8k16.row.col.f32.bf16.bf16.f32 "
        "{%0,%1,%2,%3}, {%4,%5,%6,%7}, {%8,%9}, {%0,%1,%2,%3};\n"
        : "+f"(c[0]), "+f"(c[1]), "+f"(c[2]), "+f"(c[3])
        : "r"(a[0]), "r"(a[1]), "r"(a[2]), "r"(a[3]), "r"(b[0]), "r"(b[1]));
}
__device__ __forceinline__ uint32_t lds_u32(const __nv_bfloat16* p){
    return *(const uint32_t*)p;
}
__device__ __forceinline__ uint32_t pack_bf16(float x, float y){
    __nv_bfloat162 h = __floats2bfloat162_rn(x, y);
    return *(uint32_t*)&h;
}
__device__ __forceinline__ uint32_t smem_u32(const void* p){
    uint32_t a;
    asm("{ .reg .u64 t; cvta.to.shared.u64 t, %1; cvt.u32.u64 %0, t; }" : "=r"(a) : "l"(p));
    return a;
}
__device__ __forceinline__ void cp16(uint32_t dst, const void* src){
    asm volatile("cp.async.cg.shared.global [%0], [%1], 16;" :: "r"(dst), "l"(src));
}
#define CP_COMMIT() asm volatile("cp.async.commit_group;" ::: "memory")
#define CP_WAIT0()  asm volatile("cp.async.wait_group 0;" ::: "memory")

// ---------------- proj GEMM smem geometry (static smem path) ---------------
#define SSTR 40
#define ABUF (128*SSTR)

// ---------------- attn smem geometry (dynamic) ------------------------------
#define QSTR 264
#define QOFF 0
#define QSZ  (128*QSTR*2)            // 67584
#define KOFF QSZ
#define KSTR 40
#define KBUF (128*KSTR*2)            // 10240
#define POFF (KOFF + 2*KBUF)         // 88064
#define PSTR 136
#define PSZ  (128*PSTR*2)            // 34816
#define VOFF (POFF + PSZ)            // 122880
#define VSTR 136
#define VSZ  (64*VSTR*2)             // 17408
#define SMEM_ATTN (VOFF + VSZ)       // 140288

// ---------------------------------------------------------------------------
__global__ void zero_kernel(float* out0){
    int i = blockIdx.x*blockDim.x + threadIdx.x;
    if (i < BQ) g_den[i] = 0.f;
    if (i == 0) out0[0] = 0.f;
}

// ---------------------------------------------------------------------------
// projection mainloop (fp32 src -> bf16 smem, register staged, double buffer)
__device__ __forceinline__ void proj_main(const float* __restrict__ Ag,
                                          const float* __restrict__ Bg,
                                          __nv_bfloat16* As, __nv_bfloat16* Bs,
                                          float acc[4][4][4])
{
    const int tid = threadIdx.x, lid = tid & 31, wid = tid >> 5;
    const int wm = wid & 1, wn = wid >> 1;
    const int g = lid >> 2, tig = lid & 3;
    const int r0 = tid >> 3, j = tid & 7;
    const int NK = DIN/32;

    float4 af[4], bf4[4];
    auto LDG = [&](int kc){
        #pragma unroll
        for (int i = 0; i < 4; i++)
            af[i] = *(const float4*)(Ag + (size_t)(r0 + i*32)*DIN + kc*32 + j*4);
        #pragma unroll
        for (int i = 0; i < 4; i++)
            bf4[i] = *(const float4*)(Bg + (size_t)(r0 + i*32)*DIN + kc*32 + j*4);
    };
    auto STS = [&](int buf){
        #pragma unroll
        for (int i = 0; i < 4; i++){
            uint2 v = { pack_bf16(af[i].x, af[i].y), pack_bf16(af[i].z, af[i].w) };
            *(uint2*)(As + buf*ABUF + (r0 + i*32)*SSTR + j*4) = v;
        }
        #pragma unroll
        for (int i = 0; i < 4; i++){
            uint2 v = { pack_bf16(bf4[i].x, bf4[i].y), pack_bf16(bf4[i].z, bf4[i].w) };
            *(uint2*)(Bs + buf*ABUF + (r0 + i*32)*SSTR + j*4) = v;
        }
    };

    LDG(0); STS(0);
    __syncthreads();
    for (int kc = 0; kc < NK; kc++){
        const int buf = kc & 1;
        if (kc + 1 < NK) LDG(kc + 1);
        const __nv_bfloat16* Ab = As + buf*ABUF;
        const __nv_bfloat16* Bb = Bs + buf*ABUF;
        #pragma unroll
        for (int ks = 0; ks < 2; ks++){
            uint32_t afr[4][4];
            #pragma unroll
            for (int mf = 0; mf < 4; mf++){
                const int row = wm*64 + mf*16 + g;
                const int col = ks*16 + 2*tig;
                afr[mf][0] = lds_u32(Ab + row*SSTR + col);
                afr[mf][1] = lds_u32(Ab + (row+8)*SSTR + col);
                afr[mf][2] = lds_u32(Ab + row*SSTR + col + 8);
                afr[mf][3] = lds_u32(Ab + (row+8)*SSTR + col + 8);
            }
            uint32_t bfr[4][2];
            #pragma unroll
            for (int nf = 0; nf < 4; nf++){
                const int n = wn*32 + nf*8 + g;
                bfr[nf][0] = lds_u32(Bb + n*SSTR + ks*16 + 2*tig);
                bfr[nf][1] = lds_u32(Bb + n*SSTR + ks*16 + 2*tig + 8);
            }
            #pragma unroll
            for (int mf = 0; mf < 4; mf++)
                #pragma unroll
                for (int nf = 0; nf < 4; nf++)
                    mma_bf16(acc[mf][nf], afr[mf], bfr[nf]);
        }
        if (kc + 1 < NK){
            __syncthreads();
            STS((kc + 1) & 1);
            __syncthreads();
        }
    }
}

__global__ __launch_bounds__(256) void proj_kernel(const float* __restrict__ A,
                                                   const float* __restrict__ W){
    __shared__ __nv_bfloat16 As[2*ABUF];
    __shared__ __nv_bfloat16 Bs[2*ABUF];
    const int m0 = blockIdx.x * 128, n0 = blockIdx.y * 128;
    float acc[4][4][4] = {};
    proj_main(A + (size_t)m0*DIN, W + (size_t)n0*DIN, As, Bs, acc);

    const int lid = threadIdx.x & 31, wid = threadIdx.x >> 5;
    const int wm = wid & 1, wn = wid >> 1;
    const int g = lid >> 2, tig = lid & 3;
    #pragma unroll
    for (int mf = 0; mf < 4; mf++){
        const int rlo = m0 + wm*64 + mf*16 + g;
        #pragma unroll
        for (int nf = 0; nf < 4; nf++){
            const int cb = n0 + wn*32 + nf*8 + tig*2;
            *(float2*)(g_F + (size_t)rlo*DF + cb)     = make_float2(acc[mf][nf][0], acc[mf][nf][1]);
            *(float2*)(g_F + (size_t)(rlo+8)*DF + cb) = make_float2(acc[mf][nf][2], acc[mf][nf][3]);
        }
    }
}

// ---------------------------------------------------------------------------
// L2 row normalize fp32 -> bf16, width DF=256, 64 threads/row
__global__ void l2norm_kernel(__nv_bfloat16* __restrict__ outp){
    __shared__ float ws[2];
    const int r = blockIdx.x, t = threadIdx.x;
    float4 v = *(const float4*)(g_F + (size_t)r*DF + t*4);
    float ss = v.x*v.x + v.y*v.y + v.z*v.z + v.w*v.w;
    #pragma unroll
    for (int o = 16; o > 0; o >>= 1) ss += __shfl_down_sync(0xffffffffu, ss, o);
    if ((t & 31) == 0) ws[t>>5] = ss;
    __syncthreads();
    float inv = 1.f / fmaxf(sqrtf(ws[0] + ws[1]), 1e-12f);
    uint2 o = { pack_bf16(v.x*inv, v.y*inv), pack_bf16(v.z*inv, v.w*inv) };
    *(uint2*)(outp + (size_t)r*DF + t*4) = o;
}

// ---------------------------------------------------------------------------
// g_Vt[d][r] = (l1norm(ex_classes[r]) @ class_reps)[d], bf16
__global__ void exrep_kernel(const float* __restrict__ exc,
                             const float* __restrict__ creps){
    __shared__ float cs[NLAB*DC];
    __shared__ float rowv[NLAB];
    const int r = blockIdx.x, t = threadIdx.x;
    for (int i = t; i < NLAB*DC; i += 64) cs[i] = creps[i];
    if (t < NLAB) rowv[t] = exc[(size_t)r*NLAB + t];
    __syncthreads();
    float s = 0.f;
    #pragma unroll
    for (int k = 0; k < NLAB; k++) s += fabsf(rowv[k]);
    float inv = 1.f / fmaxf(s, 1e-12f);
    float acc = 0.f;
    #pragma unroll
    for (int k = 0; k < NLAB; k++) acc += rowv[k]*cs[k*DC + t];
    g_Vt[(size_t)t*NEX + r] = __float2bfloat16_rn(acc*inv);
}

// ---------------------------------------------------------------------------
// Fused attention: per CTA, q-block 128 x key-split 2048.
// S = Q.K^T (bf16 MMA), a = s^3, den += |a| (regs), P = bf16(a) -> smem,
// num += P.V^T (bf16 MMA, accumulated in regs over all 16 tiles).
__global__ __launch_bounds__(256) void attn_kernel(){
    extern __shared__ char smem[];
    const uint32_t sb = smem_u32(smem);
    const int tid = threadIdx.x, lid = tid & 31, wid = tid >> 5;
    const int wm = wid & 1, wn = wid >> 1;
    const int g = lid >> 2, tig = lid & 3;
    const int q0 = blockIdx.x * 128;
    const int split = blockIdx.y;
    const int k0 = split * KSPLIT;

    const __nv_bfloat16* Qs = (const __nv_bfloat16*)(smem + QOFF);
    const __nv_bfloat16* Ps = (const __nv_bfloat16*)(smem + POFF);
    const __nv_bfloat16* Vs = (const __nv_bfloat16*)(smem + VOFF);

    auto load_K = [&](int n0, int kc, int buf){
        #pragma unroll
        for (int i = 0; i < 2; i++){
            int idx = tid + i*256;
            int row = idx >> 2, seg = idx & 3;
            cp16(sb + KOFF + buf*KBUF + (row*KSTR + seg*8)*2,
                 g_Kh + (size_t)(k0 + n0 + row)*DF + kc*32 + seg*8);
        }
    };

    // Q tile (128 x 256) + first K chunk
    #pragma unroll
    for (int i = 0; i < 16; i++){
        int idx = tid + i*256;
        int row = idx >> 5, seg = idx & 31;
        cp16(sb + QOFF + (row*QSTR + seg*8)*2,
             g_Qh + (size_t)(q0 + row)*DF + seg*8);
    }
    load_K(0, 0, 0);
    CP_COMMIT();
    CP_WAIT0();
    __syncthreads();

    float num[4][2][4] = {};
    float den0[4] = {}, den1[4] = {};
    int cur = 0;

    for (int t = 0; t < TILES; t++){
        const int n0 = t*128;
        // V tile for this key-tile (overlaps with S mainloop)
        #pragma unroll
        for (int i = 0; i < 4; i++){
            int idx = tid + i*256;
            int row = idx >> 4, seg = idx & 15;
            cp16(sb + VOFF + (row*VSTR + seg*8)*2,
                 g_Vt + (size_t)row*NEX + k0 + n0 + seg*8);
        }
        CP_COMMIT();

        float sacc[4][4][4] = {};
        #pragma unroll 1
        for (int kc = 0; kc < 8; kc++){
            const int buf = cur;
            const bool has_next = !(t == TILES-1 && kc == 7);
            if (has_next){
                const int nt  = (kc == 7) ? n0 + 128 : n0;
                const int nkc = (kc == 7) ? 0 : kc + 1;
                load_K(nt, nkc, buf ^ 1);
                CP_COMMIT();
            }
            const __nv_bfloat16* Kb = (const __nv_bfloat16*)(smem + KOFF + buf*KBUF);
            #pragma unroll
            for (int ks = 0; ks < 2; ks++){
                uint32_t afr[4][4];
                #pragma unroll
                for (int mf = 0; mf < 4; mf++){
                    const int row = wm*64 + mf*16 + g;
                    const int col = kc*32 + ks*16 + 2*tig;
                    afr[mf][0] = lds_u32(Qs + row*QSTR + col);
                    afr[mf][1] = lds_u32(Qs + (row+8)*QSTR + col);
                    afr[mf][2] = lds_u32(Qs + row*QSTR + col + 8);
                    afr[mf][3] = lds_u32(Qs + (row+8)*QSTR + col + 8);
                }
                uint32_t bfr[4][2];
                #pragma unroll
                for (int nf = 0; nf < 4; nf++){
                    const int n = wn*32 + nf*8 + g;
                    bfr[nf][0] = lds_u32(Kb + n*KSTR + ks*16 + 2*tig);
                    bfr[nf][1] = lds_u32(Kb + n*KSTR + ks*16 + 2*tig + 8);
                }
                #pragma unroll
                for (int mf = 0; mf < 4; mf++)
                    #pragma unroll
                    for (int nf = 0; nf < 4; nf++)
                        mma_bf16(sacc[mf][nf], afr[mf], bfr[nf]);
            }
            CP_WAIT0();
            __syncthreads();
            cur ^= 1;
        }

        // epilogue: a = s^3, den, pack into P
        __nv_bfloat16* Pw = (__nv_bfloat16*)(smem + POFF);
        #pragma unroll
        for (int mf = 0; mf < 4; mf++){
            const int rlo = wm*64 + mf*16 + g;
            #pragma unroll
            for (int nf = 0; nf < 4; nf++){
                const int cb = wn*32 + nf*8 + tig*2;
                float s0 = sacc[mf][nf][0], s1 = sacc[mf][nf][1];
                float s2 = sacc[mf][nf][2], s3 = sacc[mf][nf][3];
                float a0 = s0*s0*s0, a1 = s1*s1*s1, a2 = s2*s2*s2, a3 = s3*s3*s3;
                den0[mf] += fabsf(a0) + fabsf(a1);
                den1[mf] += fabsf(a2) + fabsf(a3);
                *(uint32_t*)(Pw + rlo*PSTR + cb)     = pack_bf16(a0, a1);
                *(uint32_t*)(Pw + (rlo+8)*PSTR + cb) = pack_bf16(a2, a3);
            }
        }
        __syncthreads();   // P + V visible to all warps

        // PV: num[128x64] += P[128x128] . Vt[64x128]^T
        #pragma unroll
        for (int ks = 0; ks < 8; ks++){
            uint32_t afr[4][4];
            #pragma unroll
            for (int mf = 0; mf < 4; mf++){
                const int row = wm*64 + mf*16 + g;
                const int col = ks*16 + 2*tig;
                afr[mf][0] = lds_u32(Ps + row*PSTR + col);
                afr[mf][1] = lds_u32(Ps + (row+8)*PSTR + col);
                afr[mf][2] = lds_u32(Ps + row*PSTR + col + 8);
                afr[mf][3] = lds_u32(Ps + (row+8)*PSTR + col + 8);
            }
            uint32_t bfr[2][2];
            #pragma unroll
            for (int nf = 0; nf < 2; nf++){
                const int d = wn*16 + nf*8 + g;
                bfr[nf][0] = lds_u32(Vs + d*VSTR + ks*16 + 2*tig);
                bfr[nf][1] = lds_u32(Vs + d*VSTR + ks*16 + 2*tig + 8);
            }
            #pragma unroll
            for (int mf = 0; mf < 4; mf++)
                #pragma unroll
                for (int nf = 0; nf < 2; nf++)
                    mma_bf16(num[mf][nf], afr[mf], bfr[nf]);
        }
        __syncthreads();   // before P/V overwritten next tile
    }

    // den: reduce over tig, cross-warp via smem, one atomic per row
    float* sden = (float*)smem;   // reuse Q region
    if (tid < 128) sden[tid] = 0.f;
    __syncthreads();
    #pragma unroll
    for (int mf = 0; mf < 4; mf++){
        float d0 = den0[mf], d1 = den1[mf];
        d0 += __shfl_xor_sync(0xffffffffu, d0, 1);
        d0 += __shfl_xor_sync(0xffffffffu, d0, 2);
        d1 += __shfl_xor_sync(0xffffffffu, d1, 1);
        d1 += __shfl_xor_sync(0xffffffffu, d1, 2);
        if (tig == 0){
            atomicAdd(&sden[wm*64 + mf*16 + g], d0);
            atomicAdd(&sden[wm*64 + mf*16 + g + 8], d1);
        }
    }
    __syncthreads();
    if (tid < 128) atomicAdd(&g_den[q0 + tid], sden[tid]);

    // num -> g_num8[split]
    float* outb = g_num8 + (size_t)split*BQ*DC;
    #pragma unroll
    for (int mf = 0; mf < 4; mf++){
        const int rlo = q0 + wm*64 + mf*16 + g;
        #pragma unroll
        for (int nf = 0; nf < 2; nf++){
            const int cb = wn*16 + nf*8 + tig*2;
            *(float2*)(outb + (size_t)rlo*DC + cb)     = make_float2(num[mf][nf][0], num[mf][nf][1]);
            *(float2*)(outb + (size_t)(rlo+8)*DC + cb) = make_float2(num[mf][nf][2], num[mf][nf][3]);
        }
    }
}

// ---------------------------------------------------------------------------
// echo = (sum_splits num8)/max(den,eps); neg_dists = -||echo - class_reps||; BCE mean
__global__ void loss_kernel(const float* __restrict__ labels,
                            const float* __restrict__ creps,
                            float* __restrict__ out){
    __shared__ float echo_s[DC];
    const int b = blockIdx.x, t = threadIdx.x;
    float inv = 1.f / fmaxf(g_den[b], 1e-12f);
    float n0 = 0.f, n1 = 0.f;
    #pragma unroll
    for (int s = 0; s < PV_SPLITS; s++){
        const float* p = g_num8 + ((size_t)s*BQ + b)*DC;
        n0 += p[t];
        n1 += p[t + 32];
    }
    echo_s[t]      = n0 * inv;
    echo_s[t + 32] = n1 * inv;
    __syncwarp();
    float le = 0.f;
    if (t < NLAB){
        float ss = 0.f;
        #pragma unroll
        for (int d = 0; d < DC; d++){
            float df = echo_s[d] - creps[t*DC + d];
            ss += df*df;
        }
        float x = -sqrtf(ss);
        out[1 + (size_t)b*NLAB + t] = x;
        float y = labels[(size_t)b*NLAB + t];
        le = log1pf(expf(x)) - y*x;
    }
    #pragma unroll
    for (int o = 16; o > 0; o >>= 1) le += __shfl_down_sync(0xffffffffu, le, o);
    if (t == 0) atomicAdd(out, le * (1.f/((float)BQ*(float)NLAB)));
}

// ---------------------------------------------------------------------------
extern "C" void kernel_launch(void* const* d_in, const int* in_sizes, int n_in,
                              void* d_out, int out_size){
    const float* features    = (const float*)d_in[0];
    const float* labels      = (const float*)d_in[1];
    const float* ex_features = (const float*)d_in[2];
    const float* ex_classes  = (const float*)d_in[3];
    const float* g_w         = (const float*)d_in[4];
    const float* class_reps  = (const float*)d_in[5];
    float* out = (float*)d_out;

    __nv_bfloat16 *pQ, *pK;
    cudaGetSymbolAddress((void**)&pQ, g_Qh);
    cudaGetSymbolAddress((void**)&pK, g_Kh);

    cudaFuncSetAttribute(attn_kernel, cudaFuncAttributeMaxDynamicSharedMemorySize, SMEM_ATTN);

    zero_kernel<<<(BQ + 255)/256, 256>>>(out);

    // Q path (g_F reused: proj -> l2norm before next proj)
    proj_kernel<<<dim3(BQ/128, 2), 256>>>(features, g_w);
    l2norm_kernel<<<BQ, 64>>>(pQ);
    // K path
    proj_kernel<<<dim3(NEX/128, 2), 256>>>(ex_features, g_w);
    l2norm_kernel<<<NEX, 64>>>(pK);

    exrep_kernel<<<NEX, 64>>>(ex_classes, class_reps);
    attn_kernel<<<dim3(BQ/128, PV_SPLITS), 256, SMEM_ATTN>>>();
    loss_kernel<<<BQ, 32>>>(labels, class_reps, out);
}

// round 13
// speedup vs baseline: 8.0257x; 1.2807x over previous
#include <cuda_runtime.h>
#include <cuda_bf16.h>
#include <math.h>
#include <stdint.h>

#define BQ   4096
#define NEX  16384
#define DIN  1024
#define DF   256
#define NLAB 28
#define DC   64
#define PV_SPLITS 8
#define KSPLIT (NEX/PV_SPLITS)   // 2048
#define TILES (KSPLIT/128)       // 16

// ---------------- scratch (device globals: allocation-free rule) ----------
__device__ __nv_bfloat16  g_FhB[(size_t)BQ*DIN];      // features bf16
__device__ __nv_bfloat16  g_Xh[(size_t)NEX*DIN];      // ex_features bf16
__device__ __nv_bfloat16  g_Wh[(size_t)DF*DIN];       // g_w bf16
__device__ __nv_bfloat16  g_Qh[(size_t)BQ*DF];        // l2-normed queries (bf16)
__device__ __nv_bfloat16  g_Kh[(size_t)NEX*DF];       // l2-normed exemplars (bf16)
__device__ __nv_bfloat16  g_Vt[(size_t)DC*NEX];       // V transposed (bf16)
__device__ float          g_num8[(size_t)PV_SPLITS*BQ*DC];
__device__ float          g_den[BQ];

// ---------------- helpers ---------------------------------------------------
__device__ __forceinline__ void mma_bf16(float c[4], const uint32_t a[4], const uint32_t b[2]){
    asm volatile(
        "mma.sync.aligned.m16n8k16.row.col.f32.bf16.bf16.f32 "
        "{%0,%1,%2,%3}, {%4,%5,%6,%7}, {%8,%9}, {%0,%1,%2,%3};\n"
        : "+f"(c[0]), "+f"(c[1]), "+f"(c[2]), "+f"(c[3])
        : "r"(a[0]), "r"(a[1]), "r"(a[2]), "r"(a[3]), "r"(b[0]), "r"(b[1]));
}
__device__ __forceinline__ uint32_t lds_u32(const __nv_bfloat16* p){
    return *(const uint32_t*)p;
}
__device__ __forceinline__ uint32_t pack_bf16(float x, float y){
    __nv_bfloat162 h = __floats2bfloat162_rn(x, y);
    return *(uint32_t*)&h;
}
__device__ __forceinline__ uint32_t smem_u32(const void* p){
    uint32_t a;
    asm("{ .reg .u64 t; cvta.to.shared.u64 t, %1; cvt.u32.u64 %0, t; }" : "=r"(a) : "l"(p));
    return a;
}
__device__ __forceinline__ void cp16(uint32_t dst, const void* src){
    asm volatile("cp.async.cg.shared.global [%0], [%1], 16;" :: "r"(dst), "l"(src));
}
#define CP_COMMIT() asm volatile("cp.async.commit_group;" ::: "memory")
#define CP_WAIT1()  asm volatile("cp.async.wait_group 1;" ::: "memory")
#define CP_WAIT2()  asm volatile("cp.async.wait_group 2;" ::: "memory")

// ---------------- attn smem geometry (dynamic) ------------------------------
#define QSTR 264
#define QOFF 0
#define QSZ  (128*QSTR*2)            // 67584
#define KOFF QSZ
#define KSTR 136
#define KBUF (128*KSTR*2)            // 34816 bytes per buffer
#define VOFF (KOFF + 2*KBUF)         // 137216
#define VSTR 136
#define VSZ  (64*VSTR*2)             // 17408
#define SMEM_ATTN (VOFF + VSZ)       // 154624

// ---------------- proj smem geometry (dynamic) ------------------------------
#define PASTR 72
#define PABUF (128*PASTR)            // elems per A buffer
#define PBSTR 72
#define PBBUF (256*PBSTR)            // elems per B buffer
#define PROJ_BOFF (2*PABUF*2)        // 36864 bytes
#define SMEM_PROJ (PROJ_BOFF + 2*PBBUF*2)   // 110592

// ---------------------------------------------------------------------------
__global__ void zero_kernel(float* out0){
    int i = blockIdx.x*blockDim.x + threadIdx.x;
    if (i < BQ) g_den[i] = 0.f;
    if (i == 0) out0[0] = 0.f;
}

// ---------------------------------------------------------------------------
// fp32 -> bf16 bulk convert, 8 elems/thread
__global__ void conv_kernel(const float* __restrict__ src,
                            __nv_bfloat16* __restrict__ dst, int n8){
    int i = blockIdx.x*blockDim.x + threadIdx.x;
    if (i >= n8) return;
    const float4* s = (const float4*)src + (size_t)i*2;
    float4 a = s[0], b = s[1];
    uint4 o = { pack_bf16(a.x,a.y), pack_bf16(a.z,a.w),
                pack_bf16(b.x,b.y), pack_bf16(b.z,b.w) };
    *((uint4*)dst + i) = o;
}

// ---------------------------------------------------------------------------
// projection + fused L2 normalize: out[m] = l2norm(X[m] @ W^T) in bf16
// BM=128, BN=256 (full row), BK=64, cp.async double-buffered, warps 2(M)x4(N)
__global__ __launch_bounds__(256, 1) void proj_kernel(){
    extern __shared__ char smem[];
    const uint32_t sb = smem_u32(smem);
    const int tid = threadIdx.x, lid = tid & 31, wid = tid >> 5;
    const int wm = wid & 1, wn = wid >> 1;
    const int g = lid >> 2, tig = lid & 3;
    const int m0 = blockIdx.x * 128;

    const __nv_bfloat16* Asrc;
    __nv_bfloat16* outp;
    if (m0 < BQ){ Asrc = g_FhB + (size_t)m0*DIN;        outp = g_Qh + (size_t)m0*DF; }
    else        { Asrc = g_Xh + (size_t)(m0-BQ)*DIN;    outp = g_Kh + (size_t)(m0-BQ)*DF; }

    auto loadC = [&](int kc, int buf){
        #pragma unroll
        for (int i = 0; i < 4; i++){
            int idx = tid + i*256, row = idx >> 3, seg = idx & 7;
            cp16(sb + buf*(PABUF*2) + (row*PASTR + seg*8)*2,
                 Asrc + (size_t)row*DIN + kc*64 + seg*8);
        }
        #pragma unroll
        for (int i = 0; i < 8; i++){
            int idx = tid + i*256, row = idx >> 3, seg = idx & 7;
            cp16(sb + PROJ_BOFF + buf*(PBBUF*2) + (row*PBSTR + seg*8)*2,
                 g_Wh + (size_t)row*DIN + kc*64 + seg*8);
        }
    };
    loadC(0, 0); CP_COMMIT();
    loadC(1, 1); CP_COMMIT();

    float acc[4][8][4] = {};
    const __nv_bfloat16* As = (const __nv_bfloat16*)smem;
    const __nv_bfloat16* Bs = (const __nv_bfloat16*)(smem + PROJ_BOFF);

    for (int kc = 0; kc < 16; kc++){
        CP_WAIT1();
        __syncthreads();
        const __nv_bfloat16* Ab = As + (kc & 1)*PABUF;
        const __nv_bfloat16* Bb = Bs + (kc & 1)*PBBUF;
        #pragma unroll
        for (int ks = 0; ks < 4; ks++){
            uint32_t afr[4][4];
            #pragma unroll
            for (int mf = 0; mf < 4; mf++){
                const int row = wm*64 + mf*16 + g;
                const int col = ks*16 + 2*tig;
                afr[mf][0] = lds_u32(Ab + row*PASTR + col);
                afr[mf][1] = lds_u32(Ab + (row+8)*PASTR + col);
                afr[mf][2] = lds_u32(Ab + row*PASTR + col + 8);
                afr[mf][3] = lds_u32(Ab + (row+8)*PASTR + col + 8);
            }
            uint32_t bfr[8][2];
            #pragma unroll
            for (int nf = 0; nf < 8; nf++){
                const int n = wn*64 + nf*8 + g;
                bfr[nf][0] = lds_u32(Bb + n*PBSTR + ks*16 + 2*tig);
                bfr[nf][1] = lds_u32(Bb + n*PBSTR + ks*16 + 2*tig + 8);
            }
            #pragma unroll
            for (int mf = 0; mf < 4; mf++)
                #pragma unroll
                for (int nf = 0; nf < 8; nf++)
                    mma_bf16(acc[mf][nf], afr[mf], bfr[nf]);
        }
        __syncthreads();
        if (kc + 2 < 16) loadC(kc + 2, kc & 1);
        CP_COMMIT();
    }

    // fused L2 norm: per-row sum of squares via smem atomics
    float* srow = (float*)smem;
    __syncthreads();
    if (tid < 128) srow[tid] = 0.f;
    __syncthreads();
    #pragma unroll
    for (int mf = 0; mf < 4; mf++){
        float ss0 = 0.f, ss1 = 0.f;
        #pragma unroll
        for (int nf = 0; nf < 8; nf++){
            ss0 += acc[mf][nf][0]*acc[mf][nf][0] + acc[mf][nf][1]*acc[mf][nf][1];
            ss1 += acc[mf][nf][2]*acc[mf][nf][2] + acc[mf][nf][3]*acc[mf][nf][3];
        }
        ss0 += __shfl_xor_sync(0xffffffffu, ss0, 1);
        ss0 += __shfl_xor_sync(0xffffffffu, ss0, 2);
        ss1 += __shfl_xor_sync(0xffffffffu, ss1, 1);
        ss1 += __shfl_xor_sync(0xffffffffu, ss1, 2);
        if (tig == 0){
            atomicAdd(&srow[wm*64 + mf*16 + g], ss0);
            atomicAdd(&srow[wm*64 + mf*16 + g + 8], ss1);
        }
    }
    __syncthreads();
    #pragma unroll
    for (int mf = 0; mf < 4; mf++){
        const int row = wm*64 + mf*16 + g;
        float i0 = 1.f / fmaxf(sqrtf(srow[row]),     1e-12f);
        float i1 = 1.f / fmaxf(sqrtf(srow[row + 8]), 1e-12f);
        #pragma unroll
        for (int nf = 0; nf < 8; nf++){
            const int col = wn*64 + nf*8 + 2*tig;
            *(uint32_t*)(outp + (size_t)row*DF + col) =
                pack_bf16(acc[mf][nf][0]*i0, acc[mf][nf][1]*i0);
            *(uint32_t*)(outp + (size_t)(row+8)*DF + col) =
                pack_bf16(acc[mf][nf][2]*i1, acc[mf][nf][3]*i1);
        }
    }
}

// ---------------------------------------------------------------------------
// g_Vt[d][r] = (l1norm(ex_classes[r]) @ class_reps)[d], bf16, coalesced writes
__global__ __launch_bounds__(256) void exrep_kernel(const float* __restrict__ exc,
                                                    const float* __restrict__ creps){
    __shared__ float cs[NLAB*DC];
    __shared__ float ex_s[64*NLAB];
    __shared__ float inv_s[64];
    const int r0 = blockIdx.x*64, tid = threadIdx.x;
    for (int i = tid; i < NLAB*DC; i += 256) cs[i] = creps[i];
    for (int i = tid; i < 64*NLAB; i += 256) ex_s[i] = exc[(size_t)r0*NLAB + i];
    __syncthreads();
    if (tid < 64){
        float s = 0.f;
        #pragma unroll
        for (int k = 0; k < NLAB; k++) s += fabsf(ex_s[tid*NLAB + k]);
        inv_s[tid] = 1.f / fmaxf(s, 1e-12f);
    }
    __syncthreads();
    const int d = tid & 63, rb = tid >> 6;
    uint32_t ov[8];
    #pragma unroll
    for (int rr = 0; rr < 16; rr += 2){
        const int ra = rb*16 + rr;
        float a0 = 0.f, a1 = 0.f;
        #pragma unroll
        for (int k = 0; k < NLAB; k++){
            float c = cs[k*DC + d];
            a0 += ex_s[ra*NLAB + k] * c;
            a1 += ex_s[(ra+1)*NLAB + k] * c;
        }
        ov[rr >> 1] = pack_bf16(a0*inv_s[ra], a1*inv_s[ra+1]);
    }
    __nv_bfloat16* dst = g_Vt + (size_t)d*NEX + r0 + rb*16;
    *(uint4*)dst       = make_uint4(ov[0], ov[1], ov[2], ov[3]);
    *((uint4*)dst + 1) = make_uint4(ov[4], ov[5], ov[6], ov[7]);
}

// ---------------------------------------------------------------------------
// Fused attention: q-block 128 x key-split 2048. Warps 4(M) x 2(N).
// S = Q.K^T (per-warp 32q x 64k), a = s^3 in regs, PV from REGISTERS
// (accumulator fragments repacked as A-operands), num reduced across the
// 2 N-warps at the end. K streamed in 32KB chunks 2-deep via cp.async.
__global__ __launch_bounds__(256, 1) void attn_kernel(){
    extern __shared__ char smem[];
    const uint32_t sb = smem_u32(smem);
    const int tid = threadIdx.x, lid = tid & 31, wid = tid >> 5;
    const int wm = wid & 3, wn = wid >> 2;          // 4 M-warps x 2 N-warps
    const int g = lid >> 2, tig = lid & 3;
    const int q0 = blockIdx.x * 128;
    const int split = blockIdx.y;
    const int k0 = split * KSPLIT;

    const __nv_bfloat16* Qs = (const __nv_bfloat16*)(smem + QOFF);
    const __nv_bfloat16* Vs = (const __nv_bfloat16*)(smem + VOFF);

    auto load_K = [&](int tile, int c, int buf){
        const size_t nb = (size_t)(k0 + tile*128);
        #pragma unroll
        for (int i = 0; i < 8; i++){
            int idx = tid + i*256, row = idx >> 4, seg = idx & 15;
            cp16(sb + KOFF + buf*KBUF + (row*KSTR + seg*8)*2,
                 g_Kh + (nb + row)*DF + c*128 + seg*8);
        }
    };
    auto load_V = [&](int tile){
        #pragma unroll
        for (int i = 0; i < 4; i++){
            int idx = tid + i*256, row = idx >> 4, seg = idx & 15;
            cp16(sb + VOFF + (row*VSTR + seg*8)*2,
                 g_Vt + (size_t)row*NEX + k0 + tile*128 + seg*8);
        }
    };

    // prologue: G0 = {Q, K chunk0}, G1 = {K chunk1}, G2 = {V tile0}
    #pragma unroll
    for (int i = 0; i < 16; i++){
        int idx = tid + i*256, row = idx >> 5, seg = idx & 31;
        cp16(sb + QOFF + (row*QSTR + seg*8)*2,
             g_Qh + (size_t)(q0 + row)*DF + seg*8);
    }
    load_K(0, 0, 0); CP_COMMIT();
    load_K(0, 1, 1); CP_COMMIT();
    load_V(0);       CP_COMMIT();

    float num[2][8][4] = {};
    float den[2][2] = {};

    for (int t = 0; t < TILES; t++){
        float sacc[2][8][4] = {};
        // ---- S phase: 2 feature-chunks of 128 ----
        #pragma unroll 1
        for (int c = 0; c < 2; c++){
            CP_WAIT2();
            __syncthreads();
            const __nv_bfloat16* Kb = (const __nv_bfloat16*)(smem + KOFF + c*KBUF);
            #pragma unroll
            for (int ks = 0; ks < 8; ks++){
                uint32_t afr[2][4];
                #pragma unroll
                for (int mf = 0; mf < 2; mf++){
                    const int row = wm*32 + mf*16 + g;
                    const int col = c*128 + ks*16 + 2*tig;
                    afr[mf][0] = lds_u32(Qs + row*QSTR + col);
                    afr[mf][1] = lds_u32(Qs + (row+8)*QSTR + col);
                    afr[mf][2] = lds_u32(Qs + row*QSTR + col + 8);
                    afr[mf][3] = lds_u32(Qs + (row+8)*QSTR + col + 8);
                }
                uint32_t bfr[8][2];
                #pragma unroll
                for (int nf = 0; nf < 8; nf++){
                    const int n = wn*64 + nf*8 + g;
                    bfr[nf][0] = lds_u32(Kb + n*KSTR + ks*16 + 2*tig);
                    bfr[nf][1] = lds_u32(Kb + n*KSTR + ks*16 + 2*tig + 8);
                }
                #pragma unroll
                for (int mf = 0; mf < 2; mf++)
                    #pragma unroll
                    for (int nf = 0; nf < 8; nf++)
                        mma_bf16(sacc[mf][nf], afr[mf], bfr[nf]);
            }
            __syncthreads();                       // readers done with buf c
            const int j = 2*t + c + 2;             // chunk index to prefetch
            if (j < 2*TILES) load_K(j >> 1, j & 1, j & 1);
            CP_COMMIT();                           // uniform (empty at tail)
        }

        // ---- transform: a = s^3, den accumulation (registers) ----
        #pragma unroll
        for (int mf = 0; mf < 2; mf++)
            #pragma unroll
            for (int nf = 0; nf < 8; nf++){
                float a0 = sacc[mf][nf][0]; a0 = a0*a0*a0;
                float a1 = sacc[mf][nf][1]; a1 = a1*a1*a1;
                float a2 = sacc[mf][nf][2]; a2 = a2*a2*a2;
                float a3 = sacc[mf][nf][3]; a3 = a3*a3*a3;
                den[mf][0] += fabsf(a0) + fabsf(a1);
                den[mf][1] += fabsf(a2) + fabsf(a3);
                sacc[mf][nf][0] = a0; sacc[mf][nf][1] = a1;
                sacc[mf][nf][2] = a2; sacc[mf][nf][3] = a3;
            }

        // ---- PV phase: A-operands packed straight from sacc ----
        CP_WAIT2();                                // V(t) guaranteed
        __syncthreads();
        #pragma unroll
        for (int kst = 0; kst < 4; kst++){
            uint32_t av[2][4];
            #pragma unroll
            for (int mf = 0; mf < 2; mf++){
                av[mf][0] = pack_bf16(sacc[mf][2*kst][0],   sacc[mf][2*kst][1]);
                av[mf][1] = pack_bf16(sacc[mf][2*kst][2],   sacc[mf][2*kst][3]);
                av[mf][2] = pack_bf16(sacc[mf][2*kst+1][0], sacc[mf][2*kst+1][1]);
                av[mf][3] = pack_bf16(sacc[mf][2*kst+1][2], sacc[mf][2*kst+1][3]);
            }
            #pragma unroll
            for (int dt = 0; dt < 8; dt++){
                const int d = dt*8 + g;
                uint32_t bv[2];
                bv[0] = lds_u32(Vs + d*VSTR + wn*64 + kst*16 + 2*tig);
                bv[1] = lds_u32(Vs + d*VSTR + wn*64 + kst*16 + 2*tig + 8);
                #pragma unroll
                for (int mf = 0; mf < 2; mf++)
                    mma_bf16(num[mf][dt], av[mf], bv);
            }
        }
        __syncthreads();                           // V readers done
        if (t + 1 < TILES) load_V(t + 1);
        CP_COMMIT();                               // uniform (empty at tail)
    }

    // ---- final reductions ----
    float* rbuf = (float*)smem;                    // 128 x 68 floats (34.8KB)
    float* sden = (float*)(smem + 128*68*4);
    __syncthreads();
    if (tid < 128) sden[tid] = 0.f;
    if (wn == 1){
        #pragma unroll
        for (int mf = 0; mf < 2; mf++){
            const int r = wm*32 + mf*16 + g;
            #pragma unroll
            for (int dt = 0; dt < 8; dt++){
                *(float2*)&rbuf[r*68 + dt*8 + 2*tig] =
                    make_float2(num[mf][dt][0], num[mf][dt][1]);
                *(float2*)&rbuf[(r+8)*68 + dt*8 + 2*tig] =
                    make_float2(num[mf][dt][2], num[mf][dt][3]);
            }
        }
    }
    __syncthreads();
    #pragma unroll
    for (int mf = 0; mf < 2; mf++){
        float d0 = den[mf][0], d1 = den[mf][1];
        d0 += __shfl_xor_sync(0xffffffffu, d0, 1);
        d0 += __shfl_xor_sync(0xffffffffu, d0, 2);
        d1 += __shfl_xor_sync(0xffffffffu, d1, 1);
        d1 += __shfl_xor_sync(0xffffffffu, d1, 2);
        if (tig == 0){
            atomicAdd(&sden[wm*32 + mf*16 + g], d0);
            atomicAdd(&sden[wm*32 + mf*16 + g + 8], d1);
        }
    }
    if (wn == 0){
        float* outb = g_num8 + (size_t)split*BQ*DC;
        #pragma unroll
        for (int mf = 0; mf < 2; mf++){
            const int r = wm*32 + mf*16 + g;
            #pragma unroll
            for (int dt = 0; dt < 8; dt++){
                float2 p0 = *(float2*)&rbuf[r*68 + dt*8 + 2*tig];
                float2 p1 = *(float2*)&rbuf[(r+8)*68 + dt*8 + 2*tig];
                *(float2*)(outb + (size_t)(q0 + r)*DC + dt*8 + 2*tig) =
                    make_float2(num[mf][dt][0] + p0.x, num[mf][dt][1] + p0.y);
                *(float2*)(outb + (size_t)(q0 + r + 8)*DC + dt*8 + 2*tig) =
                    make_float2(num[mf][dt][2] + p1.x, num[mf][dt][3] + p1.y);
            }
        }
    }
    __syncthreads();
    if (tid < 128) atomicAdd(&g_den[q0 + tid], sden[tid]);
}

// ---------------------------------------------------------------------------
// echo = (sum_splits num8)/max(den,eps); neg_dists = -||echo - class_reps||; BCE mean
__global__ void loss_kernel(const float* __restrict__ labels,
                            const float* __restrict__ creps,
                            float* __restrict__ out){
    __shared__ float echo_s[DC];
    const int b = blockIdx.x, t = threadIdx.x;
    float inv = 1.f / fmaxf(g_den[b], 1e-12f);
    float n0 = 0.f, n1 = 0.f;
    #pragma unroll
    for (int s = 0; s < PV_SPLITS; s++){
        const float* p = g_num8 + ((size_t)s*BQ + b)*DC;
        n0 += p[t];
        n1 += p[t + 32];
    }
    echo_s[t]      = n0 * inv;
    echo_s[t + 32] = n1 * inv;
    __syncwarp();
    float le = 0.f;
    if (t < NLAB){
        float ss = 0.f;
        #pragma unroll
        for (int d = 0; d < DC; d++){
            float df = echo_s[d] - creps[t*DC + d];
            ss += df*df;
        }
        float x = -sqrtf(ss);
        out[1 + (size_t)b*NLAB + t] = x;
        float y = labels[(size_t)b*NLAB + t];
        le = log1pf(expf(x)) - y*x;
    }
    #pragma unroll
    for (int o = 16; o > 0; o >>= 1) le += __shfl_down_sync(0xffffffffu, le, o);
    if (t == 0) atomicAdd(out, le * (1.f/((float)BQ*(float)NLAB)));
}

// ---------------------------------------------------------------------------
extern "C" void kernel_launch(void* const* d_in, const int* in_sizes, int n_in,
                              void* d_out, int out_size){
    const float* features    = (const float*)d_in[0];
    const float* labels      = (const float*)d_in[1];
    const float* ex_features = (const float*)d_in[2];
    const float* ex_classes  = (const float*)d_in[3];
    const float* g_w         = (const float*)d_in[4];
    const float* class_reps  = (const float*)d_in[5];
    float* out = (float*)d_out;

    __nv_bfloat16 *pFh, *pXh, *pWh;
    cudaGetSymbolAddress((void**)&pFh, g_FhB);
    cudaGetSymbolAddress((void**)&pXh, g_Xh);
    cudaGetSymbolAddress((void**)&pWh, g_Wh);

    static int attr_done = 0;
    if (!attr_done){
        cudaFuncSetAttribute(proj_kernel, cudaFuncAttributeMaxDynamicSharedMemorySize, SMEM_PROJ);
        cudaFuncSetAttribute(attn_kernel, cudaFuncAttributeMaxDynamicSharedMemorySize, SMEM_ATTN);
        attr_done = 1;
    }

    zero_kernel<<<(BQ + 255)/256, 256>>>(out);

    conv_kernel<<<(BQ*DIN/8 + 255)/256, 256>>>(features, pFh, BQ*DIN/8);
    conv_kernel<<<(NEX*DIN/8 + 255)/256, 256>>>(ex_features, pXh, NEX*DIN/8);
    conv_kernel<<<(DF*DIN/8 + 255)/256, 256>>>(g_w, pWh, DF*DIN/8);

    proj_kernel<<<(BQ + NEX)/128, 256, SMEM_PROJ>>>();
    exrep_kernel<<<NEX/64, 256>>>(ex_classes, class_reps);
    attn_kernel<<<dim3(BQ/128, PV_SPLITS), 256, SMEM_ATTN>>>();
    loss_kernel<<<BQ, 32>>>(labels, class_reps, out);
}

// round 14
// speedup vs baseline: 8.3358x; 1.0386x over previous
#include <cuda_runtime.h>
#include <cuda_bf16.h>
#include <math.h>
#include <stdint.h>

#define BQ   4096
#define NEX  16384
#define DIN  1024
#define DF   256
#define NLAB 28
#define DC   64
#define PV_SPLITS 8
#define KSPLIT (NEX/PV_SPLITS)   // 2048
#define TILES (KSPLIT/128)       // 16

// ---------------- scratch (device globals: allocation-free rule) ----------
__device__ __nv_bfloat16  g_FhB[(size_t)BQ*DIN];      // features bf16
__device__ __nv_bfloat16  g_Xh[(size_t)NEX*DIN];      // ex_features bf16
__device__ __nv_bfloat16  g_Wh[(size_t)DF*DIN];       // g_w bf16
__device__ __nv_bfloat16  g_Qh[(size_t)BQ*DF];        // l2-normed queries (bf16)
__device__ __nv_bfloat16  g_Kh[(size_t)NEX*DF];       // l2-normed exemplars (bf16)
__device__ __nv_bfloat16  g_Vt[(size_t)DC*NEX];       // V transposed (bf16)
__device__ float          g_num8[(size_t)PV_SPLITS*BQ*DC];
__device__ float          g_den[BQ];

// ---------------- helpers ---------------------------------------------------
__device__ __forceinline__ void mma_bf16(float c[4], const uint32_t a[4], const uint32_t b[2]){
    asm volatile(
        "mma.sync.aligned.m16n8k16.row.col.f32.bf16.bf16.f32 "
        "{%0,%1,%2,%3}, {%4,%5,%6,%7}, {%8,%9}, {%0,%1,%2,%3};\n"
        : "+f"(c[0]), "+f"(c[1]), "+f"(c[2]), "+f"(c[3])
        : "r"(a[0]), "r"(a[1]), "r"(a[2]), "r"(a[3]), "r"(b[0]), "r"(b[1]));
}
__device__ __forceinline__ void ldsm4(uint32_t& r0, uint32_t& r1, uint32_t& r2, uint32_t& r3,
                                      uint32_t addr){
    asm volatile("ldmatrix.sync.aligned.m8n8.x4.shared.b16 {%0,%1,%2,%3}, [%4];"
        : "=r"(r0), "=r"(r1), "=r"(r2), "=r"(r3) : "r"(addr));
}
__device__ __forceinline__ uint32_t pack_bf16(float x, float y){
    __nv_bfloat162 h = __floats2bfloat162_rn(x, y);
    return *(uint32_t*)&h;
}
__device__ __forceinline__ uint32_t smem_u32(const void* p){
    uint32_t a;
    asm("{ .reg .u64 t; cvta.to.shared.u64 t, %1; cvt.u32.u64 %0, t; }" : "=r"(a) : "l"(p));
    return a;
}
__device__ __forceinline__ void cp16(uint32_t dst, const void* src){
    asm volatile("cp.async.cg.shared.global [%0], [%1], 16;" :: "r"(dst), "l"(src));
}
#define CP_COMMIT() asm volatile("cp.async.commit_group;" ::: "memory")
#define CP_WAIT1()  asm volatile("cp.async.wait_group 1;" ::: "memory")
#define CP_WAIT2()  asm volatile("cp.async.wait_group 2;" ::: "memory")

// ---------------- attn smem geometry (dynamic) ------------------------------
#define QSTR 264
#define QOFF 0
#define QSZ  (128*QSTR*2)            // 67584
#define KOFF QSZ
#define KSTR 136
#define KBUF (128*KSTR*2)            // 34816 bytes per buffer
#define VOFF (KOFF + 2*KBUF)         // 137216
#define VSTR 136
#define VSZ  (64*VSTR*2)             // 17408
#define SMEM_ATTN (VOFF + VSZ)       // 154624

// ---------------- proj smem geometry (dynamic, occ-2) -----------------------
#define PASTR 40
#define PABUF (64*PASTR)             // elems per A buffer (BM=64)
#define PBSTR 40
#define PBBUF (256*PBSTR)            // elems per B buffer (BN=256)
#define PROJ_BOFF (2*PABUF*2)        // 10240 bytes
#define SMEM_PROJ (PROJ_BOFF + 2*PBBUF*2)   // 51200 bytes

// ---------------------------------------------------------------------------
__global__ void zero_kernel(float* out0){
    int i = blockIdx.x*blockDim.x + threadIdx.x;
    if (i < BQ) g_den[i] = 0.f;
    if (i == 0) out0[0] = 0.f;
}

// ---------------------------------------------------------------------------
// fp32 -> bf16 bulk convert, 8 elems/thread
__global__ void conv_kernel(const float* __restrict__ src,
                            __nv_bfloat16* __restrict__ dst, int n8){
    int i = blockIdx.x*blockDim.x + threadIdx.x;
    if (i >= n8) return;
    const float4* s = (const float4*)src + (size_t)i*2;
    float4 a = s[0], b = s[1];
    uint4 o = { pack_bf16(a.x,a.y), pack_bf16(a.z,a.w),
                pack_bf16(b.x,b.y), pack_bf16(b.z,b.w) };
    *((uint4*)dst + i) = o;
}

// ---------------------------------------------------------------------------
// projection + fused L2 normalize: out[m] = l2norm(X[m] @ W^T) in bf16
// BM=64, BN=256, BK=32, cp.async double-buffered, warps 2(M)x4(N), occ 2
__global__ __launch_bounds__(256, 2) void proj_kernel(){
    extern __shared__ char smem[];
    const uint32_t sb = smem_u32(smem);
    const int tid = threadIdx.x, lid = tid & 31, wid = tid >> 5;
    const int wm = wid & 1, wn = wid >> 1;
    const int g = lid >> 2, tig = lid & 3;
    const int m0 = blockIdx.x * 64;

    const __nv_bfloat16* Asrc;
    __nv_bfloat16* outp;
    if (m0 < BQ){ Asrc = g_FhB + (size_t)m0*DIN;        outp = g_Qh + (size_t)m0*DF; }
    else        { Asrc = g_Xh + (size_t)(m0-BQ)*DIN;    outp = g_Kh + (size_t)(m0-BQ)*DF; }

    auto loadC = [&](int kc, int buf){
        {   // A: 64 rows x 32 = 256 x 16B
            int row = tid >> 2, seg = tid & 3;
            cp16(sb + buf*(PABUF*2) + (row*PASTR + seg*8)*2,
                 Asrc + (size_t)row*DIN + kc*32 + seg*8);
        }
        #pragma unroll
        for (int i = 0; i < 4; i++){   // B: 256 rows x 32 = 1024 x 16B
            int idx = tid + i*256, row = idx >> 2, seg = idx & 3;
            cp16(sb + PROJ_BOFF + buf*(PBBUF*2) + (row*PBSTR + seg*8)*2,
                 g_Wh + (size_t)row*DIN + kc*32 + seg*8);
        }
    };
    loadC(0, 0); CP_COMMIT();
    loadC(1, 1); CP_COMMIT();

    // ldmatrix lane geometry
    const int arow_l = lid & 15;           // A/B row-within-16 block
    const int acol_l = (lid >> 4) * 8;     // A col half (k)
    const int brow_l = ((lid >> 4) << 3) + (lid & 7);   // B n-row within 16
    const int badd_l = ((lid >> 3) & 1) * 8;            // B k half

    float acc[2][8][4] = {};

    for (int kc = 0; kc < 32; kc++){
        CP_WAIT1();
        __syncthreads();
        const uint32_t Ab = sb + (kc & 1)*(PABUF*2);
        const uint32_t Bb = sb + PROJ_BOFF + (kc & 1)*(PBBUF*2);
        #pragma unroll
        for (int ks = 0; ks < 2; ks++){
            uint32_t afr[2][4];
            #pragma unroll
            for (int mf = 0; mf < 2; mf++)
                ldsm4(afr[mf][0], afr[mf][1], afr[mf][2], afr[mf][3],
                      Ab + ((wm*32 + mf*16 + arow_l)*PASTR + ks*16 + acol_l)*2);
            uint32_t bfr[8][2];
            #pragma unroll
            for (int nb = 0; nb < 4; nb++)
                ldsm4(bfr[2*nb][0], bfr[2*nb][1], bfr[2*nb+1][0], bfr[2*nb+1][1],
                      Bb + ((wn*64 + nb*16 + brow_l)*PBSTR + ks*16 + badd_l)*2);
            #pragma unroll
            for (int mf = 0; mf < 2; mf++)
                #pragma unroll
                for (int nf = 0; nf < 8; nf++)
                    mma_bf16(acc[mf][nf], afr[mf], bfr[nf]);
        }
        __syncthreads();
        if (kc + 2 < 32) loadC(kc + 2, kc & 1);
        CP_COMMIT();
    }

    // fused L2 norm: per-row sum of squares via smem atomics
    float* srow = (float*)smem;
    __syncthreads();
    if (tid < 64) srow[tid] = 0.f;
    __syncthreads();
    #pragma unroll
    for (int mf = 0; mf < 2; mf++){
        float ss0 = 0.f, ss1 = 0.f;
        #pragma unroll
        for (int nf = 0; nf < 8; nf++){
            ss0 += acc[mf][nf][0]*acc[mf][nf][0] + acc[mf][nf][1]*acc[mf][nf][1];
            ss1 += acc[mf][nf][2]*acc[mf][nf][2] + acc[mf][nf][3]*acc[mf][nf][3];
        }
        ss0 += __shfl_xor_sync(0xffffffffu, ss0, 1);
        ss0 += __shfl_xor_sync(0xffffffffu, ss0, 2);
        ss1 += __shfl_xor_sync(0xffffffffu, ss1, 1);
        ss1 += __shfl_xor_sync(0xffffffffu, ss1, 2);
        if (tig == 0){
            atomicAdd(&srow[wm*32 + mf*16 + g], ss0);
            atomicAdd(&srow[wm*32 + mf*16 + g + 8], ss1);
        }
    }
    __syncthreads();
    #pragma unroll
    for (int mf = 0; mf < 2; mf++){
        const int row = wm*32 + mf*16 + g;
        float i0 = 1.f / fmaxf(sqrtf(srow[row]),     1e-12f);
        float i1 = 1.f / fmaxf(sqrtf(srow[row + 8]), 1e-12f);
        #pragma unroll
        for (int nf = 0; nf < 8; nf++){
            const int col = wn*64 + nf*8 + 2*tig;
            *(uint32_t*)(outp + (size_t)row*DF + col) =
                pack_bf16(acc[mf][nf][0]*i0, acc[mf][nf][1]*i0);
            *(uint32_t*)(outp + (size_t)(row+8)*DF + col) =
                pack_bf16(acc[mf][nf][2]*i1, acc[mf][nf][3]*i1);
        }
    }
}

// ---------------------------------------------------------------------------
// g_Vt[d][r] = (l1norm(ex_classes[r]) @ class_reps)[d], bf16, coalesced writes
__global__ __launch_bounds__(256) void exrep_kernel(const float* __restrict__ exc,
                                                    const float* __restrict__ creps){
    __shared__ float cs[NLAB*DC];
    __shared__ float ex_s[64*NLAB];
    __shared__ float inv_s[64];
    const int r0 = blockIdx.x*64, tid = threadIdx.x;
    for (int i = tid; i < NLAB*DC; i += 256) cs[i] = creps[i];
    for (int i = tid; i < 64*NLAB; i += 256) ex_s[i] = exc[(size_t)r0*NLAB + i];
    __syncthreads();
    if (tid < 64){
        float s = 0.f;
        #pragma unroll
        for (int k = 0; k < NLAB; k++) s += fabsf(ex_s[tid*NLAB + k]);
        inv_s[tid] = 1.f / fmaxf(s, 1e-12f);
    }
    __syncthreads();
    const int d = tid & 63, rb = tid >> 6;
    uint32_t ov[8];
    #pragma unroll
    for (int rr = 0; rr < 16; rr += 2){
        const int ra = rb*16 + rr;
        float a0 = 0.f, a1 = 0.f;
        #pragma unroll
        for (int k = 0; k < NLAB; k++){
            float c = cs[k*DC + d];
            a0 += ex_s[ra*NLAB + k] * c;
            a1 += ex_s[(ra+1)*NLAB + k] * c;
        }
        ov[rr >> 1] = pack_bf16(a0*inv_s[ra], a1*inv_s[ra+1]);
    }
    __nv_bfloat16* dst = g_Vt + (size_t)d*NEX + r0 + rb*16;
    *(uint4*)dst       = make_uint4(ov[0], ov[1], ov[2], ov[3]);
    *((uint4*)dst + 1) = make_uint4(ov[4], ov[5], ov[6], ov[7]);
}

// ---------------------------------------------------------------------------
// Fused attention: q-block 128 x key-split 2048. Warps 4(M) x 2(N).
// All fragments via ldmatrix.x4; PV from registers (sacc repacked as A ops).
__global__ __launch_bounds__(256, 1) void attn_kernel(){
    extern __shared__ char smem[];
    const uint32_t sb = smem_u32(smem);
    const int tid = threadIdx.x, lid = tid & 31, wid = tid >> 5;
    const int wm = wid & 3, wn = wid >> 2;          // 4 M-warps x 2 N-warps
    const int g = lid >> 2, tig = lid & 3;
    const int q0 = blockIdx.x * 128;
    const int split = blockIdx.y;
    const int k0 = split * KSPLIT;

    auto load_K = [&](int tile, int c, int buf){
        const size_t nb = (size_t)(k0 + tile*128);
        #pragma unroll
        for (int i = 0; i < 8; i++){
            int idx = tid + i*256, row = idx >> 4, seg = idx & 15;
            cp16(sb + KOFF + buf*KBUF + (row*KSTR + seg*8)*2,
                 g_Kh + (nb + row)*DF + c*128 + seg*8);
        }
    };
    auto load_V = [&](int tile){
        #pragma unroll
        for (int i = 0; i < 4; i++){
            int idx = tid + i*256, row = idx >> 4, seg = idx & 15;
            cp16(sb + VOFF + (row*VSTR + seg*8)*2,
                 g_Vt + (size_t)row*NEX + k0 + tile*128 + seg*8);
        }
    };

    // prologue: G0 = {Q, K chunk0}, G1 = {K chunk1}, G2 = {V tile0}
    #pragma unroll
    for (int i = 0; i < 16; i++){
        int idx = tid + i*256, row = idx >> 5, seg = idx & 31;
        cp16(sb + QOFF + (row*QSTR + seg*8)*2,
             g_Qh + (size_t)(q0 + row)*DF + seg*8);
    }
    load_K(0, 0, 0); CP_COMMIT();
    load_K(0, 1, 1); CP_COMMIT();
    load_V(0);       CP_COMMIT();

    // ldmatrix lane geometry
    const int arow_l = lid & 15;
    const int acol_l = (lid >> 4) * 8;
    const int brow_l = ((lid >> 4) << 3) + (lid & 7);
    const int badd_l = ((lid >> 3) & 1) * 8;

    float num[2][8][4] = {};
    float den[2][2] = {};

    for (int t = 0; t < TILES; t++){
        float sacc[2][8][4] = {};
        // ---- S phase: 2 feature-chunks of 128 ----
        #pragma unroll 1
        for (int c = 0; c < 2; c++){
            CP_WAIT2();
            __syncthreads();
            const uint32_t Kb = sb + KOFF + c*KBUF;
            #pragma unroll
            for (int ks = 0; ks < 8; ks++){
                uint32_t afr[2][4];
                #pragma unroll
                for (int mf = 0; mf < 2; mf++)
                    ldsm4(afr[mf][0], afr[mf][1], afr[mf][2], afr[mf][3],
                          sb + QOFF + ((wm*32 + mf*16 + arow_l)*QSTR
                                        + c*128 + ks*16 + acol_l)*2);
                uint32_t bfr[8][2];
                #pragma unroll
                for (int nb = 0; nb < 4; nb++)
                    ldsm4(bfr[2*nb][0], bfr[2*nb][1], bfr[2*nb+1][0], bfr[2*nb+1][1],
                          Kb + ((wn*64 + nb*16 + brow_l)*KSTR + ks*16 + badd_l)*2);
                #pragma unroll
                for (int mf = 0; mf < 2; mf++)
                    #pragma unroll
                    for (int nf = 0; nf < 8; nf++)
                        mma_bf16(sacc[mf][nf], afr[mf], bfr[nf]);
            }
            __syncthreads();                       // readers done with buf c
            const int j = 2*t + c + 2;             // chunk index to prefetch
            if (j < 2*TILES) load_K(j >> 1, j & 1, j & 1);
            CP_COMMIT();                           // uniform (empty at tail)
        }

        // ---- transform: a = s^3, den accumulation (registers) ----
        #pragma unroll
        for (int mf = 0; mf < 2; mf++)
            #pragma unroll
            for (int nf = 0; nf < 8; nf++){
                float a0 = sacc[mf][nf][0]; a0 = a0*a0*a0;
                float a1 = sacc[mf][nf][1]; a1 = a1*a1*a1;
                float a2 = sacc[mf][nf][2]; a2 = a2*a2*a2;
                float a3 = sacc[mf][nf][3]; a3 = a3*a3*a3;
                den[mf][0] += fabsf(a0) + fabsf(a1);
                den[mf][1] += fabsf(a2) + fabsf(a3);
                sacc[mf][nf][0] = a0; sacc[mf][nf][1] = a1;
                sacc[mf][nf][2] = a2; sacc[mf][nf][3] = a3;
            }

        // ---- PV phase: A-operands packed straight from sacc, V via ldsm ----
        CP_WAIT2();                                // V(t) guaranteed
        __syncthreads();
        #pragma unroll
        for (int kst = 0; kst < 4; kst++){
            uint32_t av[2][4];
            #pragma unroll
            for (int mf = 0; mf < 2; mf++){
                av[mf][0] = pack_bf16(sacc[mf][2*kst][0],   sacc[mf][2*kst][1]);
                av[mf][1] = pack_bf16(sacc[mf][2*kst][2],   sacc[mf][2*kst][3]);
                av[mf][2] = pack_bf16(sacc[mf][2*kst+1][0], sacc[mf][2*kst+1][1]);
                av[mf][3] = pack_bf16(sacc[mf][2*kst+1][2], sacc[mf][2*kst+1][3]);
            }
            uint32_t bv[8][2];
            #pragma unroll
            for (int db = 0; db < 4; db++)
                ldsm4(bv[2*db][0], bv[2*db][1], bv[2*db+1][0], bv[2*db+1][1],
                      sb + VOFF + ((db*16 + brow_l)*VSTR
                                    + wn*64 + kst*16 + badd_l)*2);
            #pragma unroll
            for (int dt = 0; dt < 8; dt++)
                #pragma unroll
                for (int mf = 0; mf < 2; mf++)
                    mma_bf16(num[mf][dt], av[mf], bv[dt]);
        }
        __syncthreads();                           // V readers done
        if (t + 1 < TILES) load_V(t + 1);
        CP_COMMIT();                               // uniform (empty at tail)
    }

    // ---- final reductions ----
    float* rbuf = (float*)smem;                    // 128 x 68 floats (34.8KB)
    float* sden = (float*)(smem + 128*68*4);
    __syncthreads();
    if (tid < 128) sden[tid] = 0.f;
    if (wn == 1){
        #pragma unroll
        for (int mf = 0; mf < 2; mf++){
            const int r = wm*32 + mf*16 + g;
            #pragma unroll
            for (int dt = 0; dt < 8; dt++){
                *(float2*)&rbuf[r*68 + dt*8 + 2*tig] =
                    make_float2(num[mf][dt][0], num[mf][dt][1]);
                *(float2*)&rbuf[(r+8)*68 + dt*8 + 2*tig] =
                    make_float2(num[mf][dt][2], num[mf][dt][3]);
            }
        }
    }
    __syncthreads();
    #pragma unroll
    for (int mf = 0; mf < 2; mf++){
        float d0 = den[mf][0], d1 = den[mf][1];
        d0 += __shfl_xor_sync(0xffffffffu, d0, 1);
        d0 += __shfl_xor_sync(0xffffffffu, d0, 2);
        d1 += __shfl_xor_sync(0xffffffffu, d1, 1);
        d1 += __shfl_xor_sync(0xffffffffu, d1, 2);
        if (tig == 0){
            atomicAdd(&sden[wm*32 + mf*16 + g], d0);
            atomicAdd(&sden[wm*32 + mf*16 + g + 8], d1);
        }
    }
    if (wn == 0){
        float* outb = g_num8 + (size_t)split*BQ*DC;
        #pragma unroll
        for (int mf = 0; mf < 2; mf++){
            const int r = wm*32 + mf*16 + g;
            #pragma unroll
            for (int dt = 0; dt < 8; dt++){
                float2 p0 = *(float2*)&rbuf[r*68 + dt*8 + 2*tig];
                float2 p1 = *(float2*)&rbuf[(r+8)*68 + dt*8 + 2*tig];
                *(float2*)(outb + (size_t)(q0 + r)*DC + dt*8 + 2*tig) =
                    make_float2(num[mf][dt][0] + p0.x, num[mf][dt][1] + p0.y);
                *(float2*)(outb + (size_t)(q0 + r + 8)*DC + dt*8 + 2*tig) =
                    make_float2(num[mf][dt][2] + p1.x, num[mf][dt][3] + p1.y);
            }
        }
    }
    __syncthreads();
    if (tid < 128) atomicAdd(&g_den[q0 + tid], sden[tid]);
}

// ---------------------------------------------------------------------------
// echo = (sum_splits num8)/max(den,eps); neg_dists = -||echo - class_reps||; BCE mean
__global__ void loss_kernel(const float* __restrict__ labels,
                            const float* __restrict__ creps,
                            float* __restrict__ out){
    __shared__ float echo_s[DC];
    const int b = blockIdx.x, t = threadIdx.x;
    float inv = 1.f / fmaxf(g_den[b], 1e-12f);
    float n0 = 0.f, n1 = 0.f;
    #pragma unroll
    for (int s = 0; s < PV_SPLITS; s++){
        const float* p = g_num8 + ((size_t)s*BQ + b)*DC;
        n0 += p[t];
        n1 += p[t + 32];
    }
    echo_s[t]      = n0 * inv;
    echo_s[t + 32] = n1 * inv;
    __syncwarp();
    float le = 0.f;
    if (t < NLAB){
        float ss = 0.f;
        #pragma unroll
        for (int d = 0; d < DC; d++){
            float df = echo_s[d] - creps[t*DC + d];
            ss += df*df;
        }
        float x = -sqrtf(ss);
        out[1 + (size_t)b*NLAB + t] = x;
        float y = labels[(size_t)b*NLAB + t];
        le = log1pf(expf(x)) - y*x;
    }
    #pragma unroll
    for (int o = 16; o > 0; o >>= 1) le += __shfl_down_sync(0xffffffffu, le, o);
    if (t == 0) atomicAdd(out, le * (1.f/((float)BQ*(float)NLAB)));
}

// ---------------------------------------------------------------------------
extern "C" void kernel_launch(void* const* d_in, const int* in_sizes, int n_in,
                              void* d_out, int out_size){
    const float* features    = (const float*)d_in[0];
    const float* labels      = (const float*)d_in[1];
    const float* ex_features = (const float*)d_in[2];
    const float* ex_classes  = (const float*)d_in[3];
    const float* g_w         = (const float*)d_in[4];
    const float* class_reps  = (const float*)d_in[5];
    float* out = (float*)d_out;

    __nv_bfloat16 *pFh, *pXh, *pWh;
    cudaGetSymbolAddress((void**)&pFh, g_FhB);
    cudaGetSymbolAddress((void**)&pXh, g_Xh);
    cudaGetSymbolAddress((void**)&pWh, g_Wh);

    static int attr_done = 0;
    if (!attr_done){
        cudaFuncSetAttribute(proj_kernel, cudaFuncAttributeMaxDynamicSharedMemorySize, SMEM_PROJ);
        cudaFuncSetAttribute(attn_kernel, cudaFuncAttributeMaxDynamicSharedMemorySize, SMEM_ATTN);
        attr_done = 1;
    }

    zero_kernel<<<(BQ + 255)/256, 256>>>(out);

    conv_kernel<<<(BQ*DIN/8 + 255)/256, 256>>>(features, pFh, BQ*DIN/8);
    conv_kernel<<<(NEX*DIN/8 + 255)/256, 256>>>(ex_features, pXh, NEX*DIN/8);
    conv_kernel<<<(DF*DIN/8 + 255)/256, 256>>>(g_w, pWh, DF*DIN/8);

    proj_kernel<<<(BQ + NEX)/64, 256, SMEM_PROJ>>>();
    exrep_kernel<<<NEX/64, 256>>>(ex_classes, class_reps);
    attn_kernel<<<dim3(BQ/128, PV_SPLITS), 256, SMEM_ATTN>>>();
    loss_kernel<<<BQ, 32>>>(labels, class_reps, out);
}